// round 4
// baseline (speedup 1.0000x reference)
#include <cuda_runtime.h>
#include <cuda_bf16.h>
#include <cstdint>

#define BATCH 4
#define CCH   32
#define IMG   256
#define GRID_ 32
#define TDIM  33
#define TT    (TDIM*TDIM)   // 1089
#define KSEG  1104          // one split segment (1089 padded to mult of 16)
#define KP    3328          // 3*1104 = 3312, padded to mult of 64
#define MPAD  1152          // 9 * 128
#define NREAL 2112          // 33 * 64
#define NPAD  2176          // 17 * 128

#define OFF_MR  (BATCH*CCH*IMG*IMG)        // 8388608
#define OFF_RC  (OFF_MR + BATCH*IMG*IMG)   // 8650752

// ---------------- scratch ------------------------------------------------------
__device__ __nv_bfloat16 g_A[(size_t)BATCH * MPAD * KP];  // ~30.7 MB [b][t][k']
__device__ __nv_bfloat16 g_B[(size_t)BATCH * NPAD * KP];  // ~58.0 MB [b][n][k']
__device__ int           g_ids[BATCH * GRID_ * GRID_];

// ---------------- helpers ------------------------------------------------------
__device__ __forceinline__ void cp_async16(uint32_t saddr, const void* g) {
    asm volatile("cp.async.cg.shared.global [%0], [%1], 16;\n" :: "r"(saddr), "l"(g));
}

// ---------------- K1: A' = [Ah | Ah | Al] --------------------------------------
__global__ void prep_A(const float* __restrict__ cosd) {
    int idx = blockIdx.x * blockDim.x + threadIdx.x;
    const int per_b = MPAD * KSEG;
    if (idx >= BATCH * per_b) return;
    int b  = idx / per_b;
    int r  = idx - b * per_b;
    int t  = r / KSEG;
    int kk = r - t * KSEG;
    float s = 0.f;
    if (t < TT && kk < TT) {
        int my = kk / TDIM, mx = kk - my * TDIM;
        int Ty = t / TDIM,  Tx = t - Ty * TDIM;
        const float* cb = cosd + (size_t)b * 1024 * 1024;
        #pragma unroll
        for (int qy = 0; qy < 2; qy++) {
            int ny = my - qy, gy = Ty - qy;
            if ((unsigned)ny < GRID_ && (unsigned)gy < GRID_) {
                #pragma unroll
                for (int qx = 0; qx < 2; qx++) {
                    int nx = mx - qx, gx = Tx - qx;
                    if ((unsigned)nx < GRID_ && (unsigned)gx < GRID_)
                        s += cb[((ny * GRID_ + nx) * GRID_ + gy) * GRID_ + gx];
                }
            }
        }
    }
    __nv_bfloat16 hi = __float2bfloat16(s);
    __nv_bfloat16 lo = __float2bfloat16(s - __bfloat162float(hi));
    __nv_bfloat16* row = g_A + ((size_t)b * MPAD + t) * KP;
    row[kk]            = hi;
    row[kk + KSEG]     = hi;
    row[kk + 2 * KSEG] = lo;
}

// ---------------- K2: B' = [Bh | Bl | Bh] --------------------------------------
__global__ void prep_B(const float* __restrict__ bimg, const float* __restrict__ mask) {
    int idx = blockIdx.x * blockDim.x + threadIdx.x;
    const int per_b = NPAD * KSEG;
    if (idx >= BATCH * per_b) return;
    int b  = idx / per_b;
    int r  = idx - b * per_b;
    int n  = r / KSEG;
    int kk = r - n * KSEG;
    float val = 0.f;
    if (kk < TT && n < NREAL) {
        int my = kk / TDIM, mx = kk - my * TDIM;
        int c  = n >> 6;
        int dy = (n >> 3) & 7;
        int dx = n & 7;
        int u = my * 8 + dy - 4; u = max(0, min(IMG - 1, u));
        int v = mx * 8 + dx - 4; v = max(0, min(IMG - 1, v));
        float m = mask[(b * IMG + u) * IMG + v];
        if (c < CCH) val = bimg[((b * CCH + c) * IMG + u) * IMG + v] * (1.f - m);
        else         val = m;
    }
    __nv_bfloat16 hi = __float2bfloat16(val);
    __nv_bfloat16 lo = __float2bfloat16(val - __bfloat162float(hi));
    __nv_bfloat16* row = g_B + ((size_t)b * NPAD + n) * KP;
    row[kk]            = hi;
    row[kk + KSEG]     = lo;
    row[kk + 2 * KSEG] = hi;
}

// ---------------- K3: zero-pad k' in [3312, 3328) ------------------------------
__global__ void pad_K() {
    int idx = blockIdx.x * blockDim.x + threadIdx.x;
    const int nA = BATCH * MPAD * 16;
    const int nB = BATCH * NPAD * 16;
    if (idx < nA) {
        int b = idx / (MPAD * 16); int r = idx - b * MPAD * 16;
        g_A[((size_t)b * MPAD + r / 16) * KP + 3312 + (r & 15)] = __float2bfloat16(0.f);
    } else if (idx < nA + nB) {
        idx -= nA;
        int b = idx / (NPAD * 16); int r = idx - b * NPAD * 16;
        g_B[((size_t)b * NPAD + r / 16) * KP + 3312 + (r & 15)] = __float2bfloat16(0.f);
    }
}

// ---------------- K4: HMMA GEMM 128x128x32, 3-stage cp.async pipeline ----------
#define BM 128
#define BN 128
#define BK 32
#define NK (KP / BK)     // 104
#define SSTR 40          // bf16 row stride (80 B): conflict-free ldmatrix
#define ASTG (BM * SSTR)
#define STG  (2 * ASTG)                 // A + B per stage (elements)
#define SMEM_BYTES (3 * STG * 2)        // 61440 B

__global__ void __launch_bounds__(256, 2) gemm_mma(float* __restrict__ out) {
    extern __shared__ __nv_bfloat16 sm[];

    const int tid = threadIdx.x, lane = tid & 31, wid = tid >> 5;
    const int wm = wid >> 2, wn = wid & 3;          // 2 x 4 warp grid
    const int b  = blockIdx.z;
    const int t0 = blockIdx.x * BM;
    const int n0 = blockIdx.y * BN;

    const __nv_bfloat16* Ab = g_A + ((size_t)b * MPAD + t0) * KP;
    const __nv_bfloat16* Bb = g_B + ((size_t)b * NPAD + n0) * KP;

    float acc[4][4][4];
    #pragma unroll
    for (int mi = 0; mi < 4; mi++)
        #pragma unroll
        for (int ni = 0; ni < 4; ni++)
            #pragma unroll
            for (int r = 0; r < 4; r++) acc[mi][ni][r] = 0.f;

    auto loadTile = [&](int kc, int st) {
        __nv_bfloat16* As = sm + st * STG;
        __nv_bfloat16* Bs = As + ASTG;
        #pragma unroll
        for (int q = 0; q < 2; q++) {
            int idx = tid + q * 256;
            int row = idx >> 2, cc = (idx & 3) * 8;
            cp_async16((uint32_t)__cvta_generic_to_shared(As + row * SSTR + cc),
                       Ab + (size_t)row * KP + kc * BK + cc);
        }
        #pragma unroll
        for (int q = 0; q < 2; q++) {
            int idx = tid + q * 256;
            int row = idx >> 2, cc = (idx & 3) * 8;
            cp_async16((uint32_t)__cvta_generic_to_shared(Bs + row * SSTR + cc),
                       Bb + (size_t)row * KP + kc * BK + cc);
        }
        asm volatile("cp.async.commit_group;");
    };

    loadTile(0, 0);
    loadTile(1, 1);

    for (int kt = 0; kt < NK; kt++) {
        const int s = kt % 3;
        if (kt + 2 < NK) {
            loadTile(kt + 2, (kt + 2) % 3);
            asm volatile("cp.async.wait_group 2;" ::: "memory");
        } else if (kt + 1 < NK) {
            asm volatile("cp.async.wait_group 1;" ::: "memory");
        } else {
            asm volatile("cp.async.wait_group 0;" ::: "memory");
        }
        __syncthreads();

        __nv_bfloat16* As = sm + s * STG;
        __nv_bfloat16* Bs = As + ASTG;
        #pragma unroll
        for (int ks = 0; ks < 2; ks++) {
            uint32_t a[4][4], bf[4][2];
            #pragma unroll
            for (int mi = 0; mi < 4; mi++) {
                uint32_t ad = (uint32_t)__cvta_generic_to_shared(
                    As + (wm * 64 + mi * 16 + (lane & 15)) * SSTR + ks * 16 + (lane >> 4) * 8);
                asm volatile("ldmatrix.sync.aligned.m8n8.x4.shared.b16 {%0,%1,%2,%3}, [%4];"
                    : "=r"(a[mi][0]), "=r"(a[mi][1]), "=r"(a[mi][2]), "=r"(a[mi][3]) : "r"(ad));
            }
            #pragma unroll
            for (int ni = 0; ni < 4; ni++) {
                uint32_t bd = (uint32_t)__cvta_generic_to_shared(
                    Bs + (wn * 32 + ni * 8 + (lane & 7)) * SSTR + ks * 16 + ((lane >> 3) & 1) * 8);
                asm volatile("ldmatrix.sync.aligned.m8n8.x2.shared.b16 {%0,%1}, [%2];"
                    : "=r"(bf[ni][0]), "=r"(bf[ni][1]) : "r"(bd));
            }
            #pragma unroll
            for (int mi = 0; mi < 4; mi++)
                #pragma unroll
                for (int ni = 0; ni < 4; ni++)
                    asm volatile(
                        "mma.sync.aligned.m16n8k16.row.col.f32.bf16.bf16.f32 "
                        "{%0,%1,%2,%3}, {%4,%5,%6,%7}, {%8,%9}, {%0,%1,%2,%3};"
                        : "+f"(acc[mi][ni][0]), "+f"(acc[mi][ni][1]),
                          "+f"(acc[mi][ni][2]), "+f"(acc[mi][ni][3])
                        : "r"(a[mi][0]), "r"(a[mi][1]), "r"(a[mi][2]), "r"(a[mi][3]),
                          "r"(bf[ni][0]), "r"(bf[ni][1]));
        }
        __syncthreads();
    }

    // ---- epilogue: D[t, n] -> cropped output / mask_recon ----
    #pragma unroll
    for (int mi = 0; mi < 4; mi++) {
        #pragma unroll
        for (int rr = 0; rr < 2; rr++) {
            int t = t0 + wm * 64 + mi * 16 + (lane >> 2) + rr * 8;
            if (t >= TT) continue;
            int Ty = t / TDIM, Tx = t - Ty * TDIM;
            int cnt = ((Ty >= 1) + (Ty <= 31)) * ((Tx >= 1) + (Tx <= 31));
            float inv = 1.f / (float)cnt;
            #pragma unroll
            for (int ni = 0; ni < 4; ni++) {
                int n = n0 + wn * 32 + ni * 8 + (lane & 3) * 2;
                int c = n >> 6;
                if (c > CCH) continue;      // N padding
                int dy = (n >> 3) & 7, dx = n & 7;
                int py = Ty * 8 + dy - 4;
                if ((unsigned)py >= 256u) continue;
                int px = Tx * 8 + dx - 4;
                float sc = (c < CCH) ? 1.f : inv;
                float* dst = (c < CCH)
                    ? out + (((size_t)(b * CCH + c)) * IMG + py) * IMG
                    : out + OFF_MR + (((size_t)b) * IMG + py) * IMG;
                float v0 = acc[mi][ni][rr * 2]     * sc;
                float v1 = acc[mi][ni][rr * 2 + 1] * sc;
                if ((unsigned)px < 255u) {
                    float2 v = make_float2(v0, v1);
                    *(float2*)(dst + px) = v;
                } else {
                    if ((unsigned)px < 256u)       dst[px]     = v0;
                    if ((unsigned)(px + 1) < 256u) dst[px + 1] = v1;
                }
            }
        }
    }
}

// ---------------- K5: argmax (MLP=4) -------------------------------------------
__global__ void argmax_kernel(const float* __restrict__ cosd) {
    int b  = blockIdx.y;
    int g  = blockIdx.x * 32 + threadIdx.x;
    int ty = threadIdx.y;
    const float* cb = cosd + (size_t)b * 1024 * 1024;
    float best = -3.4e38f;
    int   bi   = 0x7fffffff;
    for (int n0 = ty * 4; n0 < 1024; n0 += 32) {
        float v0 = cb[(n0 + 0) * 1024 + g];
        float v1 = cb[(n0 + 1) * 1024 + g];
        float v2 = cb[(n0 + 2) * 1024 + g];
        float v3 = cb[(n0 + 3) * 1024 + g];
        if (v0 > best) { best = v0; bi = n0; }
        if (v1 > best) { best = v1; bi = n0 + 1; }
        if (v2 > best) { best = v2; bi = n0 + 2; }
        if (v3 > best) { best = v3; bi = n0 + 3; }
    }
    __shared__ float sv[8][32];
    __shared__ int   si[8][32];
    sv[ty][threadIdx.x] = best;
    si[ty][threadIdx.x] = bi;
    __syncthreads();
    if (ty == 0) {
        #pragma unroll
        for (int r = 1; r < 8; r++) {
            float v = sv[r][threadIdx.x];
            int   i2 = si[r][threadIdx.x];
            if (v > best || (v == best && i2 < bi)) { best = v; bi = i2; }
        }
        g_ids[b * 1024 + g] = bi;
    }
}

// ---------------- K6: recon gather ---------------------------------------------
__global__ void recon_kernel(const float* __restrict__ aux, float* __restrict__ out) {
    int idx = blockIdx.x * blockDim.x + threadIdx.x;
    if (idx >= BATCH * 3 * IMG * IMG) return;
    int x = idx & 255;
    int y = (idx >> 8) & 255;
    int bc = idx >> 16;
    int b  = bc / 3;
    int py = y + 4, px = x + 4;
    int Ty = py >> 3, dy = py & 7;
    int Tx = px >> 3, dx = px & 7;
    const int*   ids = g_ids + b * 1024;
    const float* ab  = aux + (size_t)bc * IMG * IMG;
    float s = 0.f;
    #pragma unroll
    for (int qy = 0; qy < 2; qy++) {
        int gy = Ty - qy;
        if ((unsigned)gy >= GRID_) continue;
        int i = dy + 8 * qy;
        #pragma unroll
        for (int qx = 0; qx < 2; qx++) {
            int gx = Tx - qx;
            if ((unsigned)gx >= GRID_) continue;
            int j  = dx + 8 * qx;
            int id = ids[gy * 32 + gx];
            int u = (id >> 5) * 8 + i - 4; u = max(0, min(255, u));
            int v = (id & 31) * 8 + j - 4; v = max(0, min(255, v));
            s += ab[u * IMG + v];
        }
    }
    int cnty = (Ty >= 1) + (Ty <= 31);
    int cntx = (Tx >= 1) + (Tx <= 31);
    out[OFF_RC + idx] = s / (float)(cnty * cntx);
}

// ---------------- launch -------------------------------------------------------
extern "C" void kernel_launch(void* const* d_in, const int* in_sizes, int n_in,
                              void* d_out, int out_size) {
    const float* cosd = (const float*)d_in[0];
    const float* bimg = (const float*)d_in[1];
    const float* mask = (const float*)d_in[2];
    const float* aux  = (const float*)d_in[3];
    float* out = (float*)d_out;

    int na = BATCH * MPAD * KSEG;
    prep_A<<<(na + 255) / 256, 256>>>(cosd);

    int nb = BATCH * NPAD * KSEG;
    prep_B<<<(nb + 255) / 256, 256>>>(bimg, mask);

    int np = BATCH * (MPAD + NPAD) * 16;
    pad_K<<<(np + 255) / 256, 256>>>();

    argmax_kernel<<<dim3(32, BATCH), dim3(32, 8)>>>(cosd);

    cudaFuncSetAttribute(gemm_mma, cudaFuncAttributeMaxDynamicSharedMemorySize, SMEM_BYTES);
    gemm_mma<<<dim3(MPAD / BM, NPAD / BN, BATCH), 256, SMEM_BYTES>>>(out);

    int nr = BATCH * 3 * IMG * IMG;
    recon_kernel<<<(nr + 255) / 256, 256>>>(aux, out);
}

// round 6
// speedup vs baseline: 1.1893x; 1.1893x over previous
#include <cuda_runtime.h>
#include <cuda_bf16.h>
#include <cstdint>

#define BATCH 4
#define CCH   32
#define IMG   256
#define GRID_ 32
#define TDIM  33
#define TT    (TDIM*TDIM)   // 1089
#define KSEG  1104          // one split segment (1089 padded to mult of 16)
#define KP    3328          // 3*1104 = 3312, padded to mult of 64
#define MPAD  1152          // 9 * 128
#define NREAL 2112          // 33 * 64
#define NPAD  2176          // 17 * 128

#define OFF_MR  (BATCH*CCH*IMG*IMG)        // 8388608
#define OFF_RC  (OFF_MR + BATCH*IMG*IMG)   // 8650752

// ---------------- scratch ------------------------------------------------------
__device__ __nv_bfloat16 g_A[(size_t)BATCH * MPAD * KP];  // ~30.7 MB [b][t][k']
__device__ __nv_bfloat16 g_B[(size_t)BATCH * NPAD * KP];  // ~58.0 MB [b][n][k']
__device__ int           g_ids[BATCH * GRID_ * GRID_];

// ---------------- helpers ------------------------------------------------------
__device__ __forceinline__ void cp_async16(uint32_t saddr, const void* g) {
    asm volatile("cp.async.cg.shared.global [%0], [%1], 16;\n" :: "r"(saddr), "l"(g));
}

// ---------------- K1: A' = [Ah | Ah | Al] --------------------------------------
__global__ void prep_A(const float* __restrict__ cosd) {
    int idx = blockIdx.x * blockDim.x + threadIdx.x;
    const int per_b = MPAD * KSEG;
    if (idx >= BATCH * per_b) return;
    int b  = idx / per_b;
    int r  = idx - b * per_b;
    int t  = r / KSEG;
    int kk = r - t * KSEG;
    float s = 0.f;
    if (t < TT && kk < TT) {
        int my = kk / TDIM, mx = kk - my * TDIM;
        int Ty = t / TDIM,  Tx = t - Ty * TDIM;
        const float* cb = cosd + (size_t)b * 1024 * 1024;
        #pragma unroll
        for (int qy = 0; qy < 2; qy++) {
            int ny = my - qy, gy = Ty - qy;
            if ((unsigned)ny < GRID_ && (unsigned)gy < GRID_) {
                #pragma unroll
                for (int qx = 0; qx < 2; qx++) {
                    int nx = mx - qx, gx = Tx - qx;
                    if ((unsigned)nx < GRID_ && (unsigned)gx < GRID_)
                        s += cb[((ny * GRID_ + nx) * GRID_ + gy) * GRID_ + gx];
                }
            }
        }
    }
    __nv_bfloat16 hi = __float2bfloat16(s);
    __nv_bfloat16 lo = __float2bfloat16(s - __bfloat162float(hi));
    __nv_bfloat16* row = g_A + ((size_t)b * MPAD + t) * KP;
    row[kk]            = hi;
    row[kk + KSEG]     = hi;
    row[kk + 2 * KSEG] = lo;
}

// ---------------- K2: B' = [Bh | Bl | Bh] --------------------------------------
__global__ void prep_B(const float* __restrict__ bimg, const float* __restrict__ mask) {
    int idx = blockIdx.x * blockDim.x + threadIdx.x;
    const int per_b = NPAD * KSEG;
    if (idx >= BATCH * per_b) return;
    int b  = idx / per_b;
    int r  = idx - b * per_b;
    int n  = r / KSEG;
    int kk = r - n * KSEG;
    float val = 0.f;
    if (kk < TT && n < NREAL) {
        int my = kk / TDIM, mx = kk - my * TDIM;
        int c  = n >> 6;
        int dy = (n >> 3) & 7;
        int dx = n & 7;
        int u = my * 8 + dy - 4; u = max(0, min(IMG - 1, u));
        int v = mx * 8 + dx - 4; v = max(0, min(IMG - 1, v));
        float m = mask[(b * IMG + u) * IMG + v];
        if (c < CCH) val = bimg[((b * CCH + c) * IMG + u) * IMG + v] * (1.f - m);
        else         val = m;
    }
    __nv_bfloat16 hi = __float2bfloat16(val);
    __nv_bfloat16 lo = __float2bfloat16(val - __bfloat162float(hi));
    __nv_bfloat16* row = g_B + ((size_t)b * NPAD + n) * KP;
    row[kk]            = hi;
    row[kk + KSEG]     = lo;
    row[kk + 2 * KSEG] = hi;
}

// ---------------- K3: zero-pad k' in [3312, 3328) ------------------------------
__global__ void pad_K() {
    int idx = blockIdx.x * blockDim.x + threadIdx.x;
    const int nA = BATCH * MPAD * 16;
    const int nB = BATCH * NPAD * 16;
    if (idx < nA) {
        int b = idx / (MPAD * 16); int r = idx - b * MPAD * 16;
        g_A[((size_t)b * MPAD + r / 16) * KP + 3312 + (r & 15)] = __float2bfloat16(0.f);
    } else if (idx < nA + nB) {
        idx -= nA;
        int b = idx / (NPAD * 16); int r = idx - b * NPAD * 16;
        g_B[((size_t)b * NPAD + r / 16) * KP + 3312 + (r & 15)] = __float2bfloat16(0.f);
    }
}

// ---------------- K4: HMMA GEMM 128x128x64, 2-stage, ldmatrix.x4 B -------------
#define BM 128
#define BN 128
#define BK 64
#define NK (KP / BK)     // 52
#define SSTR 72          // bf16 row stride (144 B): conflict-free ldmatrix
#define ASTG (BM * SSTR)
#define STG  (2 * ASTG)
#define SMEM_BYTES (2 * STG * 2)   // 73728 B

__global__ void __launch_bounds__(256, 2) gemm_mma(float* __restrict__ out) {
    extern __shared__ __nv_bfloat16 sm[];

    const int tid = threadIdx.x, lane = tid & 31, wid = tid >> 5;
    const int wm = wid >> 2, wn = wid & 3;          // 2 x 4 warp grid
    const int b  = blockIdx.z;
    const int t0 = blockIdx.x * BM;
    const int n0 = blockIdx.y * BN;

    const __nv_bfloat16* Ab = g_A + ((size_t)b * MPAD + t0) * KP;
    const __nv_bfloat16* Bb = g_B + ((size_t)b * NPAD + n0) * KP;

    float acc[4][4][4];
    #pragma unroll
    for (int mi = 0; mi < 4; mi++)
        #pragma unroll
        for (int ni = 0; ni < 4; ni++)
            #pragma unroll
            for (int r = 0; r < 4; r++) acc[mi][ni][r] = 0.f;

    auto loadTile = [&](int kc, int st) {
        __nv_bfloat16* As = sm + st * STG;
        __nv_bfloat16* Bs = As + ASTG;
        #pragma unroll
        for (int q = 0; q < 4; q++) {
            int idx = tid + q * 256;
            int row = idx >> 3, cc = (idx & 7) * 8;
            cp_async16((uint32_t)__cvta_generic_to_shared(As + row * SSTR + cc),
                       Ab + (size_t)row * KP + kc * BK + cc);
        }
        #pragma unroll
        for (int q = 0; q < 4; q++) {
            int idx = tid + q * 256;
            int row = idx >> 3, cc = (idx & 7) * 8;
            cp_async16((uint32_t)__cvta_generic_to_shared(Bs + row * SSTR + cc),
                       Bb + (size_t)row * KP + kc * BK + cc);
        }
        asm volatile("cp.async.commit_group;");
    };

    loadTile(0, 0);
    for (int kt = 0; kt < NK; kt++) {
        if (kt + 1 < NK) {
            loadTile(kt + 1, (kt + 1) & 1);
            asm volatile("cp.async.wait_group 1;" ::: "memory");
        } else {
            asm volatile("cp.async.wait_group 0;" ::: "memory");
        }
        __syncthreads();

        const int s = kt & 1;
        __nv_bfloat16* As = sm + s * STG;
        __nv_bfloat16* Bs = As + ASTG;
        #pragma unroll
        for (int ks = 0; ks < 4; ks++) {
            uint32_t a[4][4], bf[2][4];
            #pragma unroll
            for (int mi = 0; mi < 4; mi++) {
                uint32_t ad = (uint32_t)__cvta_generic_to_shared(
                    As + (wm * 64 + mi * 16 + (lane & 15)) * SSTR + ks * 16 + (lane >> 4) * 8);
                asm volatile("ldmatrix.sync.aligned.m8n8.x4.shared.b16 {%0,%1,%2,%3}, [%4];"
                    : "=r"(a[mi][0]), "=r"(a[mi][1]), "=r"(a[mi][2]), "=r"(a[mi][3]) : "r"(ad));
            }
            #pragma unroll
            for (int nj = 0; nj < 2; nj++) {
                uint32_t bd = (uint32_t)__cvta_generic_to_shared(
                    Bs + (wn * 32 + nj * 16 + ((lane >> 4) & 1) * 8 + (lane & 7)) * SSTR
                       + ks * 16 + ((lane >> 3) & 1) * 8);
                asm volatile("ldmatrix.sync.aligned.m8n8.x4.shared.b16 {%0,%1,%2,%3}, [%4];"
                    : "=r"(bf[nj][0]), "=r"(bf[nj][1]), "=r"(bf[nj][2]), "=r"(bf[nj][3]) : "r"(bd));
            }
            #pragma unroll
            for (int mi = 0; mi < 4; mi++)
                #pragma unroll
                for (int ni = 0; ni < 4; ni++) {
                    int nj = ni >> 1, h = (ni & 1) * 2;
                    asm volatile(
                        "mma.sync.aligned.m16n8k16.row.col.f32.bf16.bf16.f32 "
                        "{%0,%1,%2,%3}, {%4,%5,%6,%7}, {%8,%9}, {%0,%1,%2,%3};"
                        : "+f"(acc[mi][ni][0]), "+f"(acc[mi][ni][1]),
                          "+f"(acc[mi][ni][2]), "+f"(acc[mi][ni][3])
                        : "r"(a[mi][0]), "r"(a[mi][1]), "r"(a[mi][2]), "r"(a[mi][3]),
                          "r"(bf[nj][h]), "r"(bf[nj][h + 1]));
                }
        }
        __syncthreads();
    }

    // ---- epilogue: D[t, n] -> cropped output / mask_recon ----
    #pragma unroll
    for (int mi = 0; mi < 4; mi++) {
        #pragma unroll
        for (int rr = 0; rr < 2; rr++) {
            int t = t0 + wm * 64 + mi * 16 + (lane >> 2) + rr * 8;
            if (t >= TT) continue;
            int Ty = t / TDIM, Tx = t - Ty * TDIM;
            int cnt = ((Ty >= 1) + (Ty <= 31)) * ((Tx >= 1) + (Tx <= 31));
            float inv = 1.f / (float)cnt;
            #pragma unroll
            for (int ni = 0; ni < 4; ni++) {
                int n = n0 + wn * 32 + ni * 8 + (lane & 3) * 2;
                int c = n >> 6;
                if (c > CCH) continue;      // N padding
                int dy = (n >> 3) & 7, dx = n & 7;
                int py = Ty * 8 + dy - 4;
                if ((unsigned)py >= 256u) continue;
                int px = Tx * 8 + dx - 4;
                float sc = (c < CCH) ? 1.f : inv;
                float* dst = (c < CCH)
                    ? out + (((size_t)(b * CCH + c)) * IMG + py) * IMG
                    : out + OFF_MR + (((size_t)b) * IMG + py) * IMG;
                float v0 = acc[mi][ni][rr * 2]     * sc;
                float v1 = acc[mi][ni][rr * 2 + 1] * sc;
                if ((unsigned)px < 255u) {
                    float2 v = make_float2(v0, v1);
                    *(float2*)(dst + px) = v;
                } else {
                    if ((unsigned)px < 256u)       dst[px]     = v0;
                    if ((unsigned)(px + 1) < 256u) dst[px + 1] = v1;
                }
            }
        }
    }
}

// ---------------- K5: argmax ----------------------------------------------------
__global__ void argmax_kernel(const float* __restrict__ cosd) {
    int b  = blockIdx.y;
    int g  = blockIdx.x * 32 + threadIdx.x;
    int ty = threadIdx.y;
    const float* cb = cosd + (size_t)b * 1024 * 1024;
    float best = -3.4e38f;
    int   bi   = 0x7fffffff;
    for (int n0 = ty * 4; n0 < 1024; n0 += 32) {
        float v0 = cb[(n0 + 0) * 1024 + g];
        float v1 = cb[(n0 + 1) * 1024 + g];
        float v2 = cb[(n0 + 2) * 1024 + g];
        float v3 = cb[(n0 + 3) * 1024 + g];
        if (v0 > best) { best = v0; bi = n0; }
        if (v1 > best) { best = v1; bi = n0 + 1; }
        if (v2 > best) { best = v2; bi = n0 + 2; }
        if (v3 > best) { best = v3; bi = n0 + 3; }
    }
    __shared__ float sv[8][32];
    __shared__ int   si[8][32];
    sv[ty][threadIdx.x] = best;
    si[ty][threadIdx.x] = bi;
    __syncthreads();
    if (ty == 0) {
        #pragma unroll
        for (int r = 1; r < 8; r++) {
            float v = sv[r][threadIdx.x];
            int   i2 = si[r][threadIdx.x];
            if (v > best || (v == best && i2 < bi)) { best = v; bi = i2; }
        }
        g_ids[b * 1024 + g] = bi;
    }
}

// ---------------- K6: recon gather ---------------------------------------------
__global__ void recon_kernel(const float* __restrict__ aux, float* __restrict__ out) {
    int idx = blockIdx.x * blockDim.x + threadIdx.x;
    if (idx >= BATCH * 3 * IMG * IMG) return;
    int x = idx & 255;
    int y = (idx >> 8) & 255;
    int bc = idx >> 16;
    int b  = bc / 3;
    int py = y + 4, px = x + 4;
    int Ty = py >> 3, dy = py & 7;
    int Tx = px >> 3, dx = px & 7;
    const int*   ids = g_ids + b * 1024;
    const float* ab  = aux + (size_t)bc * IMG * IMG;
    float s = 0.f;
    #pragma unroll
    for (int qy = 0; qy < 2; qy++) {
        int gy = Ty - qy;
        if ((unsigned)gy >= GRID_) continue;
        int i = dy + 8 * qy;
        #pragma unroll
        for (int qx = 0; qx < 2; qx++) {
            int gx = Tx - qx;
            if ((unsigned)gx >= GRID_) continue;
            int j  = dx + 8 * qx;
            int id = ids[gy * 32 + gx];
            int u = (id >> 5) * 8 + i - 4; u = max(0, min(255, u));
            int v = (id & 31) * 8 + j - 4; v = max(0, min(255, v));
            s += ab[u * IMG + v];
        }
    }
    int cnty = (Ty >= 1) + (Ty <= 31);
    int cntx = (Tx >= 1) + (Tx <= 31);
    out[OFF_RC + idx] = s / (float)(cnty * cntx);
}

// ---------------- launch -------------------------------------------------------
extern "C" void kernel_launch(void* const* d_in, const int* in_sizes, int n_in,
                              void* d_out, int out_size) {
    const float* cosd = (const float*)d_in[0];
    const float* bimg = (const float*)d_in[1];
    const float* mask = (const float*)d_in[2];
    const float* aux  = (const float*)d_in[3];
    float* out = (float*)d_out;

    int na = BATCH * MPAD * KSEG;
    prep_A<<<(na + 255) / 256, 256>>>(cosd);

    int nb = BATCH * NPAD * KSEG;
    prep_B<<<(nb + 255) / 256, 256>>>(bimg, mask);

    int np = BATCH * (MPAD + NPAD) * 16;
    pad_K<<<(np + 255) / 256, 256>>>();

    argmax_kernel<<<dim3(32, BATCH), dim3(32, 8)>>>(cosd);

    cudaFuncSetAttribute(gemm_mma, cudaFuncAttributeMaxDynamicSharedMemorySize, SMEM_BYTES);
    gemm_mma<<<dim3(MPAD / BM, NPAD / BN, BATCH), 256, SMEM_BYTES>>>(out);

    int nr = BATCH * 3 * IMG * IMG;
    recon_kernel<<<(nr + 255) / 256, 256>>>(aux, out);
}

// round 7
// speedup vs baseline: 1.5013x; 1.2624x over previous
#include <cuda_runtime.h>
#include <cuda_fp16.h>
#include <cstdint>

#define BATCH 4
#define CCH   32
#define IMG   256
#define GRID_ 32
#define TDIM  33
#define TT    (TDIM*TDIM)   // 1089
#define KSEG  1104          // one split segment (1089 padded to mult of 16)
#define KP    2240          // 2*1104 = 2208, padded to mult of 64
#define MPAD  1152          // 9 * 128
#define NREAL 2112          // 33 * 64
#define NPAD  2176          // 17 * 128

#define OFF_MR  (BATCH*CCH*IMG*IMG)        // 8388608
#define OFF_RC  (OFF_MR + BATCH*IMG*IMG)   // 8650752

// ---------------- scratch ------------------------------------------------------
__device__ __half g_A[(size_t)BATCH * MPAD * KP];  // ~20.6 MB [b][t][k']
__device__ __half g_B[(size_t)BATCH * NPAD * KP];  // ~39.0 MB [b][n][k']
__device__ int    g_ids[BATCH * GRID_ * GRID_];

// ---------------- helpers ------------------------------------------------------
__device__ __forceinline__ void cp_async16(uint32_t saddr, const void* g) {
    asm volatile("cp.async.cg.shared.global [%0], [%1], 16;\n" :: "r"(saddr), "l"(g));
}

// ---------------- K1: A' = [Ah | Ah]  (fp16 hi of Atilde, duplicated) ----------
__global__ void prep_A(const float* __restrict__ cosd) {
    int idx = blockIdx.x * blockDim.x + threadIdx.x;
    const int per_b = MPAD * KSEG;
    if (idx >= BATCH * per_b) return;
    int b  = idx / per_b;
    int r  = idx - b * per_b;
    int t  = r / KSEG;
    int kk = r - t * KSEG;
    float s = 0.f;
    if (t < TT && kk < TT) {
        int my = kk / TDIM, mx = kk - my * TDIM;
        int Ty = t / TDIM,  Tx = t - Ty * TDIM;
        const float* cb = cosd + (size_t)b * 1024 * 1024;
        #pragma unroll
        for (int qy = 0; qy < 2; qy++) {
            int ny = my - qy, gy = Ty - qy;
            if ((unsigned)ny < GRID_ && (unsigned)gy < GRID_) {
                #pragma unroll
                for (int qx = 0; qx < 2; qx++) {
                    int nx = mx - qx, gx = Tx - qx;
                    if ((unsigned)nx < GRID_ && (unsigned)gx < GRID_)
                        s += cb[((ny * GRID_ + nx) * GRID_ + gy) * GRID_ + gx];
                }
            }
        }
    }
    __half hi = __float2half(s);
    __half* row = g_A + ((size_t)b * MPAD + t) * KP;
    row[kk]        = hi;
    row[kk + KSEG] = hi;
}

// ---------------- K2: B' = [Bh | Bl]  (fp16 split of F) ------------------------
__global__ void prep_B(const float* __restrict__ bimg, const float* __restrict__ mask) {
    int idx = blockIdx.x * blockDim.x + threadIdx.x;
    const int per_b = NPAD * KSEG;
    if (idx >= BATCH * per_b) return;
    int b  = idx / per_b;
    int r  = idx - b * per_b;
    int n  = r / KSEG;
    int kk = r - n * KSEG;
    float val = 0.f;
    if (kk < TT && n < NREAL) {
        int my = kk / TDIM, mx = kk - my * TDIM;
        int c  = n >> 6;
        int dy = (n >> 3) & 7;
        int dx = n & 7;
        int u = my * 8 + dy - 4; u = max(0, min(IMG - 1, u));
        int v = mx * 8 + dx - 4; v = max(0, min(IMG - 1, v));
        float m = mask[(b * IMG + u) * IMG + v];
        if (c < CCH) val = bimg[((b * CCH + c) * IMG + u) * IMG + v] * (1.f - m);
        else         val = m;
    }
    __half hi = __float2half(val);
    __half lo = __float2half(val - __half2float(hi));
    __half* row = g_B + ((size_t)b * NPAD + n) * KP;
    row[kk]        = hi;
    row[kk + KSEG] = lo;
}

// ---------------- K3: zero-pad k' in [2208, 2240) ------------------------------
__global__ void pad_K() {
    int idx = blockIdx.x * blockDim.x + threadIdx.x;
    const int nA = BATCH * MPAD * 32;
    const int nB = BATCH * NPAD * 32;
    if (idx < nA) {
        int b = idx / (MPAD * 32); int r = idx - b * MPAD * 32;
        g_A[((size_t)b * MPAD + r / 32) * KP + 2208 + (r & 31)] = __float2half(0.f);
    } else if (idx < nA + nB) {
        idx -= nA;
        int b = idx / (NPAD * 32); int r = idx - b * NPAD * 32;
        g_B[((size_t)b * NPAD + r / 32) * KP + 2208 + (r & 31)] = __float2half(0.f);
    }
}

// ---------------- K4: HMMA GEMM 128x128x64, 2-stage, fp16 ----------------------
#define BM 128
#define BN 128
#define BK 64
#define NK (KP / BK)     // 35
#define SSTR 72          // fp16 row stride (144 B): conflict-free ldmatrix
#define ASTG (BM * SSTR)
#define STG  (2 * ASTG)
#define SMEM_BYTES (2 * STG * 2)   // 73728 B

__global__ void __launch_bounds__(256, 2) gemm_mma(float* __restrict__ out) {
    extern __shared__ __half sm[];

    const int tid = threadIdx.x, lane = tid & 31, wid = tid >> 5;
    const int wm = wid >> 2, wn = wid & 3;          // 2 x 4 warp grid
    const int b  = blockIdx.z;
    const int t0 = blockIdx.x * BM;
    const int n0 = blockIdx.y * BN;

    const __half* Ab = g_A + ((size_t)b * MPAD + t0) * KP;
    const __half* Bb = g_B + ((size_t)b * NPAD + n0) * KP;

    float acc[4][4][4];
    #pragma unroll
    for (int mi = 0; mi < 4; mi++)
        #pragma unroll
        for (int ni = 0; ni < 4; ni++)
            #pragma unroll
            for (int r = 0; r < 4; r++) acc[mi][ni][r] = 0.f;

    auto loadTile = [&](int kc, int st) {
        __half* As = sm + st * STG;
        __half* Bs = As + ASTG;
        #pragma unroll
        for (int q = 0; q < 4; q++) {
            int idx = tid + q * 256;
            int row = idx >> 3, cc = (idx & 7) * 8;
            cp_async16((uint32_t)__cvta_generic_to_shared(As + row * SSTR + cc),
                       Ab + (size_t)row * KP + kc * BK + cc);
        }
        #pragma unroll
        for (int q = 0; q < 4; q++) {
            int idx = tid + q * 256;
            int row = idx >> 3, cc = (idx & 7) * 8;
            cp_async16((uint32_t)__cvta_generic_to_shared(Bs + row * SSTR + cc),
                       Bb + (size_t)row * KP + kc * BK + cc);
        }
        asm volatile("cp.async.commit_group;");
    };

    loadTile(0, 0);
    for (int kt = 0; kt < NK; kt++) {
        if (kt + 1 < NK) {
            loadTile(kt + 1, (kt + 1) & 1);
            asm volatile("cp.async.wait_group 1;" ::: "memory");
        } else {
            asm volatile("cp.async.wait_group 0;" ::: "memory");
        }
        __syncthreads();

        const int s = kt & 1;
        __half* As = sm + s * STG;
        __half* Bs = As + ASTG;
        #pragma unroll
        for (int ks = 0; ks < 4; ks++) {
            uint32_t a[4][4], bf[2][4];
            #pragma unroll
            for (int mi = 0; mi < 4; mi++) {
                uint32_t ad = (uint32_t)__cvta_generic_to_shared(
                    As + (wm * 64 + mi * 16 + (lane & 15)) * SSTR + ks * 16 + (lane >> 4) * 8);
                asm volatile("ldmatrix.sync.aligned.m8n8.x4.shared.b16 {%0,%1,%2,%3}, [%4];"
                    : "=r"(a[mi][0]), "=r"(a[mi][1]), "=r"(a[mi][2]), "=r"(a[mi][3]) : "r"(ad));
            }
            #pragma unroll
            for (int nj = 0; nj < 2; nj++) {
                uint32_t bd = (uint32_t)__cvta_generic_to_shared(
                    Bs + (wn * 32 + nj * 16 + ((lane >> 4) & 1) * 8 + (lane & 7)) * SSTR
                       + ks * 16 + ((lane >> 3) & 1) * 8);
                asm volatile("ldmatrix.sync.aligned.m8n8.x4.shared.b16 {%0,%1,%2,%3}, [%4];"
                    : "=r"(bf[nj][0]), "=r"(bf[nj][1]), "=r"(bf[nj][2]), "=r"(bf[nj][3]) : "r"(bd));
            }
            #pragma unroll
            for (int mi = 0; mi < 4; mi++)
                #pragma unroll
                for (int ni = 0; ni < 4; ni++) {
                    int nj = ni >> 1, h = (ni & 1) * 2;
                    asm volatile(
                        "mma.sync.aligned.m16n8k16.row.col.f32.f16.f16.f32 "
                        "{%0,%1,%2,%3}, {%4,%5,%6,%7}, {%8,%9}, {%0,%1,%2,%3};"
                        : "+f"(acc[mi][ni][0]), "+f"(acc[mi][ni][1]),
                          "+f"(acc[mi][ni][2]), "+f"(acc[mi][ni][3])
                        : "r"(a[mi][0]), "r"(a[mi][1]), "r"(a[mi][2]), "r"(a[mi][3]),
                          "r"(bf[nj][h]), "r"(bf[nj][h + 1]));
                }
        }
        __syncthreads();
    }

    // ---- epilogue: D[t, n] -> cropped output / mask_recon ----
    #pragma unroll
    for (int mi = 0; mi < 4; mi++) {
        #pragma unroll
        for (int rr = 0; rr < 2; rr++) {
            int t = t0 + wm * 64 + mi * 16 + (lane >> 2) + rr * 8;
            if (t >= TT) continue;
            int Ty = t / TDIM, Tx = t - Ty * TDIM;
            int cnt = ((Ty >= 1) + (Ty <= 31)) * ((Tx >= 1) + (Tx <= 31));
            float inv = 1.f / (float)cnt;
            #pragma unroll
            for (int ni = 0; ni < 4; ni++) {
                int n = n0 + wn * 32 + ni * 8 + (lane & 3) * 2;
                int c = n >> 6;
                if (c > CCH) continue;      // N padding
                int dy = (n >> 3) & 7, dx = n & 7;
                int py = Ty * 8 + dy - 4;
                if ((unsigned)py >= 256u) continue;
                int px = Tx * 8 + dx - 4;
                float sc = (c < CCH) ? 1.f : inv;
                float* dst = (c < CCH)
                    ? out + (((size_t)(b * CCH + c)) * IMG + py) * IMG
                    : out + OFF_MR + (((size_t)b) * IMG + py) * IMG;
                float v0 = acc[mi][ni][rr * 2]     * sc;
                float v1 = acc[mi][ni][rr * 2 + 1] * sc;
                if ((unsigned)px < 255u) {
                    float2 v = make_float2(v0, v1);
                    *(float2*)(dst + px) = v;
                } else {
                    if ((unsigned)px < 256u)       dst[px]     = v0;
                    if ((unsigned)(px + 1) < 256u) dst[px + 1] = v1;
                }
            }
        }
    }
}

// ---------------- K5: argmax ----------------------------------------------------
__global__ void argmax_kernel(const float* __restrict__ cosd) {
    int b  = blockIdx.y;
    int g  = blockIdx.x * 32 + threadIdx.x;
    int ty = threadIdx.y;
    const float* cb = cosd + (size_t)b * 1024 * 1024;
    float best = -3.4e38f;
    int   bi   = 0x7fffffff;
    for (int n0 = ty * 4; n0 < 1024; n0 += 32) {
        float v0 = cb[(n0 + 0) * 1024 + g];
        float v1 = cb[(n0 + 1) * 1024 + g];
        float v2 = cb[(n0 + 2) * 1024 + g];
        float v3 = cb[(n0 + 3) * 1024 + g];
        if (v0 > best) { best = v0; bi = n0; }
        if (v1 > best) { best = v1; bi = n0 + 1; }
        if (v2 > best) { best = v2; bi = n0 + 2; }
        if (v3 > best) { best = v3; bi = n0 + 3; }
    }
    __shared__ float sv[8][32];
    __shared__ int   si[8][32];
    sv[ty][threadIdx.x] = best;
    si[ty][threadIdx.x] = bi;
    __syncthreads();
    if (ty == 0) {
        #pragma unroll
        for (int r = 1; r < 8; r++) {
            float v = sv[r][threadIdx.x];
            int   i2 = si[r][threadIdx.x];
            if (v > best || (v == best && i2 < bi)) { best = v; bi = i2; }
        }
        g_ids[b * 1024 + g] = bi;
    }
}

// ---------------- K6: recon gather ---------------------------------------------
__global__ void recon_kernel(const float* __restrict__ aux, float* __restrict__ out) {
    int idx = blockIdx.x * blockDim.x + threadIdx.x;
    if (idx >= BATCH * 3 * IMG * IMG) return;
    int x = idx & 255;
    int y = (idx >> 8) & 255;
    int bc = idx >> 16;
    int b  = bc / 3;
    int py = y + 4, px = x + 4;
    int Ty = py >> 3, dy = py & 7;
    int Tx = px >> 3, dx = px & 7;
    const int*   ids = g_ids + b * 1024;
    const float* ab  = aux + (size_t)bc * IMG * IMG;
    float s = 0.f;
    #pragma unroll
    for (int qy = 0; qy < 2; qy++) {
        int gy = Ty - qy;
        if ((unsigned)gy >= GRID_) continue;
        int i = dy + 8 * qy;
        #pragma unroll
        for (int qx = 0; qx < 2; qx++) {
            int gx = Tx - qx;
            if ((unsigned)gx >= GRID_) continue;
            int j  = dx + 8 * qx;
            int id = ids[gy * 32 + gx];
            int u = (id >> 5) * 8 + i - 4; u = max(0, min(255, u));
            int v = (id & 31) * 8 + j - 4; v = max(0, min(255, v));
            s += ab[u * IMG + v];
        }
    }
    int cnty = (Ty >= 1) + (Ty <= 31);
    int cntx = (Tx >= 1) + (Tx <= 31);
    out[OFF_RC + idx] = s / (float)(cnty * cntx);
}

// ---------------- launch -------------------------------------------------------
extern "C" void kernel_launch(void* const* d_in, const int* in_sizes, int n_in,
                              void* d_out, int out_size) {
    const float* cosd = (const float*)d_in[0];
    const float* bimg = (const float*)d_in[1];
    const float* mask = (const float*)d_in[2];
    const float* aux  = (const float*)d_in[3];
    float* out = (float*)d_out;

    int na = BATCH * MPAD * KSEG;
    prep_A<<<(na + 255) / 256, 256>>>(cosd);

    int nb = BATCH * NPAD * KSEG;
    prep_B<<<(nb + 255) / 256, 256>>>(bimg, mask);

    int np = BATCH * (MPAD + NPAD) * 32;
    pad_K<<<(np + 255) / 256, 256>>>();

    argmax_kernel<<<dim3(32, BATCH), dim3(32, 8)>>>(cosd);

    cudaFuncSetAttribute(gemm_mma, cudaFuncAttributeMaxDynamicSharedMemorySize, SMEM_BYTES);
    gemm_mma<<<dim3(MPAD / BM, NPAD / BN, BATCH), 256, SMEM_BYTES>>>(out);

    int nr = BATCH * 3 * IMG * IMG;
    recon_kernel<<<(nr + 255) / 256, 256>>>(aux, out);
}

// round 8
// speedup vs baseline: 2.0355x; 1.3558x over previous
#include <cuda_runtime.h>
#include <cuda_fp16.h>
#include <cstdint>

#define BATCH 4
#define CCH   32
#define IMG   256
#define GRID_ 32
#define TDIM  33
#define TT    (TDIM*TDIM)   // 1089
#define KP    1152          // 1089 padded to mult of 64 (18*64)
#define MPAD  1152          // 9 * 128
#define NREAL 2112          // 33 * 64
#define NPAD  2176          // 17 * 128

#define OFF_MR  (BATCH*CCH*IMG*IMG)        // 8388608
#define OFF_RC  (OFF_MR + BATCH*IMG*IMG)   // 8650752

// ---------------- scratch ------------------------------------------------------
__device__ __half g_A[(size_t)BATCH * MPAD * KP];  // ~10.6 MB [b][t][k]
__device__ __half g_B[(size_t)BATCH * NPAD * KP];  // ~20.1 MB [b][n][k]
__device__ int    g_ids[BATCH * GRID_ * GRID_];

// ---------------- helpers ------------------------------------------------------
__device__ __forceinline__ void cp_async16(uint32_t saddr, const void* g) {
    asm volatile("cp.async.cg.shared.global [%0], [%1], 16;\n" :: "r"(saddr), "l"(g));
}

// ---------------- K1: A = fp16(Atilde), zero-padded ----------------------------
__global__ void prep_A(const float* __restrict__ cosd) {
    int idx = blockIdx.x * blockDim.x + threadIdx.x;
    const int per_b = MPAD * KP;
    if (idx >= BATCH * per_b) return;
    int b  = idx / per_b;
    int r  = idx - b * per_b;
    int t  = r / KP;
    int kk = r - t * KP;
    float s = 0.f;
    if (t < TT && kk < TT) {
        int my = kk / TDIM, mx = kk - my * TDIM;
        int Ty = t / TDIM,  Tx = t - Ty * TDIM;
        const float* cb = cosd + (size_t)b * 1024 * 1024;
        #pragma unroll
        for (int qy = 0; qy < 2; qy++) {
            int ny = my - qy, gy = Ty - qy;
            if ((unsigned)ny < GRID_ && (unsigned)gy < GRID_) {
                #pragma unroll
                for (int qx = 0; qx < 2; qx++) {
                    int nx = mx - qx, gx = Tx - qx;
                    if ((unsigned)nx < GRID_ && (unsigned)gx < GRID_)
                        s += cb[((ny * GRID_ + nx) * GRID_ + gy) * GRID_ + gx];
                }
            }
        }
    }
    g_A[idx] = __float2half(s);
}

// ---------------- K2: B = fp16(F), zero-padded ---------------------------------
__global__ void prep_B(const float* __restrict__ bimg, const float* __restrict__ mask) {
    int idx = blockIdx.x * blockDim.x + threadIdx.x;
    const int per_b = NPAD * KP;
    if (idx >= BATCH * per_b) return;
    int b  = idx / per_b;
    int r  = idx - b * per_b;
    int n  = r / KP;
    int kk = r - n * KP;
    float val = 0.f;
    if (kk < TT && n < NREAL) {
        int my = kk / TDIM, mx = kk - my * TDIM;
        int c  = n >> 6;
        int dy = (n >> 3) & 7;
        int dx = n & 7;
        int u = my * 8 + dy - 4; u = max(0, min(IMG - 1, u));
        int v = mx * 8 + dx - 4; v = max(0, min(IMG - 1, v));
        float m = mask[(b * IMG + u) * IMG + v];
        if (c < CCH) val = bimg[((b * CCH + c) * IMG + u) * IMG + v] * (1.f - m);
        else         val = m;
    }
    g_B[idx] = __float2half(val);
}

// ---------------- K4: HMMA GEMM 128x128x64, 2-stage, fp16 ----------------------
#define BM 128
#define BN 128
#define BK 64
#define NK (KP / BK)     // 18
#define SSTR 72          // fp16 row stride (144 B): conflict-free ldmatrix
#define ASTG (BM * SSTR)
#define STG  (2 * ASTG)
#define SMEM_BYTES (2 * STG * 2)   // 73728 B

__global__ void __launch_bounds__(256, 2) gemm_mma(float* __restrict__ out) {
    extern __shared__ __half sm[];

    const int tid = threadIdx.x, lane = tid & 31, wid = tid >> 5;
    const int wm = wid >> 2, wn = wid & 3;          // 2 x 4 warp grid
    const int b  = blockIdx.z;
    const int t0 = blockIdx.x * BM;
    const int n0 = blockIdx.y * BN;

    const __half* Ab = g_A + ((size_t)b * MPAD + t0) * KP;
    const __half* Bb = g_B + ((size_t)b * NPAD + n0) * KP;

    float acc[4][4][4];
    #pragma unroll
    for (int mi = 0; mi < 4; mi++)
        #pragma unroll
        for (int ni = 0; ni < 4; ni++)
            #pragma unroll
            for (int r = 0; r < 4; r++) acc[mi][ni][r] = 0.f;

    auto loadTile = [&](int kc, int st) {
        __half* As = sm + st * STG;
        __half* Bs = As + ASTG;
        #pragma unroll
        for (int q = 0; q < 4; q++) {
            int idx = tid + q * 256;
            int row = idx >> 3, cc = (idx & 7) * 8;
            cp_async16((uint32_t)__cvta_generic_to_shared(As + row * SSTR + cc),
                       Ab + (size_t)row * KP + kc * BK + cc);
        }
        #pragma unroll
        for (int q = 0; q < 4; q++) {
            int idx = tid + q * 256;
            int row = idx >> 3, cc = (idx & 7) * 8;
            cp_async16((uint32_t)__cvta_generic_to_shared(Bs + row * SSTR + cc),
                       Bb + (size_t)row * KP + kc * BK + cc);
        }
        asm volatile("cp.async.commit_group;");
    };

    loadTile(0, 0);
    for (int kt = 0; kt < NK; kt++) {
        if (kt + 1 < NK) {
            loadTile(kt + 1, (kt + 1) & 1);
            asm volatile("cp.async.wait_group 1;" ::: "memory");
        } else {
            asm volatile("cp.async.wait_group 0;" ::: "memory");
        }
        __syncthreads();

        const int s = kt & 1;
        __half* As = sm + s * STG;
        __half* Bs = As + ASTG;
        #pragma unroll
        for (int ks = 0; ks < 4; ks++) {
            uint32_t a[4][4], bf[2][4];
            #pragma unroll
            for (int mi = 0; mi < 4; mi++) {
                uint32_t ad = (uint32_t)__cvta_generic_to_shared(
                    As + (wm * 64 + mi * 16 + (lane & 15)) * SSTR + ks * 16 + (lane >> 4) * 8);
                asm volatile("ldmatrix.sync.aligned.m8n8.x4.shared.b16 {%0,%1,%2,%3}, [%4];"
                    : "=r"(a[mi][0]), "=r"(a[mi][1]), "=r"(a[mi][2]), "=r"(a[mi][3]) : "r"(ad));
            }
            #pragma unroll
            for (int nj = 0; nj < 2; nj++) {
                uint32_t bd = (uint32_t)__cvta_generic_to_shared(
                    Bs + (wn * 32 + nj * 16 + ((lane >> 4) & 1) * 8 + (lane & 7)) * SSTR
                       + ks * 16 + ((lane >> 3) & 1) * 8);
                asm volatile("ldmatrix.sync.aligned.m8n8.x4.shared.b16 {%0,%1,%2,%3}, [%4];"
                    : "=r"(bf[nj][0]), "=r"(bf[nj][1]), "=r"(bf[nj][2]), "=r"(bf[nj][3]) : "r"(bd));
            }
            #pragma unroll
            for (int mi = 0; mi < 4; mi++)
                #pragma unroll
                for (int ni = 0; ni < 4; ni++) {
                    int nj = ni >> 1, h = (ni & 1) * 2;
                    asm volatile(
                        "mma.sync.aligned.m16n8k16.row.col.f32.f16.f16.f32 "
                        "{%0,%1,%2,%3}, {%4,%5,%6,%7}, {%8,%9}, {%0,%1,%2,%3};"
                        : "+f"(acc[mi][ni][0]), "+f"(acc[mi][ni][1]),
                          "+f"(acc[mi][ni][2]), "+f"(acc[mi][ni][3])
                        : "r"(a[mi][0]), "r"(a[mi][1]), "r"(a[mi][2]), "r"(a[mi][3]),
                          "r"(bf[nj][h]), "r"(bf[nj][h + 1]));
                }
        }
        __syncthreads();
    }

    // ---- epilogue: D[t, n] -> cropped output / mask_recon ----
    #pragma unroll
    for (int mi = 0; mi < 4; mi++) {
        #pragma unroll
        for (int rr = 0; rr < 2; rr++) {
            int t = t0 + wm * 64 + mi * 16 + (lane >> 2) + rr * 8;
            if (t >= TT) continue;
            int Ty = t / TDIM, Tx = t - Ty * TDIM;
            int cnt = ((Ty >= 1) + (Ty <= 31)) * ((Tx >= 1) + (Tx <= 31));
            float inv = 1.f / (float)cnt;
            #pragma unroll
            for (int ni = 0; ni < 4; ni++) {
                int n = n0 + wn * 32 + ni * 8 + (lane & 3) * 2;
                int c = n >> 6;
                if (c > CCH) continue;      // N padding
                int dy = (n >> 3) & 7, dx = n & 7;
                int py = Ty * 8 + dy - 4;
                if ((unsigned)py >= 256u) continue;
                int px = Tx * 8 + dx - 4;
                float sc = (c < CCH) ? 1.f : inv;
                float* dst = (c < CCH)
                    ? out + (((size_t)(b * CCH + c)) * IMG + py) * IMG
                    : out + OFF_MR + (((size_t)b) * IMG + py) * IMG;
                float v0 = acc[mi][ni][rr * 2]     * sc;
                float v1 = acc[mi][ni][rr * 2 + 1] * sc;
                if ((unsigned)px < 255u) {
                    float2 v = make_float2(v0, v1);
                    *(float2*)(dst + px) = v;
                } else {
                    if ((unsigned)px < 256u)       dst[px]     = v0;
                    if ((unsigned)(px + 1) < 256u) dst[px + 1] = v1;
                }
            }
        }
    }
}

// ---------------- K5: argmax ----------------------------------------------------
__global__ void argmax_kernel(const float* __restrict__ cosd) {
    int b  = blockIdx.y;
    int g  = blockIdx.x * 32 + threadIdx.x;
    int ty = threadIdx.y;
    const float* cb = cosd + (size_t)b * 1024 * 1024;
    float best = -3.4e38f;
    int   bi   = 0x7fffffff;
    for (int n0 = ty * 4; n0 < 1024; n0 += 32) {
        float v0 = cb[(n0 + 0) * 1024 + g];
        float v1 = cb[(n0 + 1) * 1024 + g];
        float v2 = cb[(n0 + 2) * 1024 + g];
        float v3 = cb[(n0 + 3) * 1024 + g];
        if (v0 > best) { best = v0; bi = n0; }
        if (v1 > best) { best = v1; bi = n0 + 1; }
        if (v2 > best) { best = v2; bi = n0 + 2; }
        if (v3 > best) { best = v3; bi = n0 + 3; }
    }
    __shared__ float sv[8][32];
    __shared__ int   si[8][32];
    sv[ty][threadIdx.x] = best;
    si[ty][threadIdx.x] = bi;
    __syncthreads();
    if (ty == 0) {
        #pragma unroll
        for (int r = 1; r < 8; r++) {
            float v = sv[r][threadIdx.x];
            int   i2 = si[r][threadIdx.x];
            if (v > best || (v == best && i2 < bi)) { best = v; bi = i2; }
        }
        g_ids[b * 1024 + g] = bi;
    }
}

// ---------------- K6: recon gather ---------------------------------------------
__global__ void recon_kernel(const float* __restrict__ aux, float* __restrict__ out) {
    int idx = blockIdx.x * blockDim.x + threadIdx.x;
    if (idx >= BATCH * 3 * IMG * IMG) return;
    int x = idx & 255;
    int y = (idx >> 8) & 255;
    int bc = idx >> 16;
    int b  = bc / 3;
    int py = y + 4, px = x + 4;
    int Ty = py >> 3, dy = py & 7;
    int Tx = px >> 3, dx = px & 7;
    const int*   ids = g_ids + b * 1024;
    const float* ab  = aux + (size_t)bc * IMG * IMG;
    float s = 0.f;
    #pragma unroll
    for (int qy = 0; qy < 2; qy++) {
        int gy = Ty - qy;
        if ((unsigned)gy >= GRID_) continue;
        int i = dy + 8 * qy;
        #pragma unroll
        for (int qx = 0; qx < 2; qx++) {
            int gx = Tx - qx;
            if ((unsigned)gx >= GRID_) continue;
            int j  = dx + 8 * qx;
            int id = ids[gy * 32 + gx];
            int u = (id >> 5) * 8 + i - 4; u = max(0, min(255, u));
            int v = (id & 31) * 8 + j - 4; v = max(0, min(255, v));
            s += ab[u * IMG + v];
        }
    }
    int cnty = (Ty >= 1) + (Ty <= 31);
    int cntx = (Tx >= 1) + (Tx <= 31);
    out[OFF_RC + idx] = s / (float)(cnty * cntx);
}

// ---------------- launch -------------------------------------------------------
extern "C" void kernel_launch(void* const* d_in, const int* in_sizes, int n_in,
                              void* d_out, int out_size) {
    const float* cosd = (const float*)d_in[0];
    const float* bimg = (const float*)d_in[1];
    const float* mask = (const float*)d_in[2];
    const float* aux  = (const float*)d_in[3];
    float* out = (float*)d_out;

    int na = BATCH * MPAD * KP;
    prep_A<<<(na + 255) / 256, 256>>>(cosd);

    int nb = BATCH * NPAD * KP;
    prep_B<<<(nb + 255) / 256, 256>>>(bimg, mask);

    argmax_kernel<<<dim3(32, BATCH), dim3(32, 8)>>>(cosd);

    cudaFuncSetAttribute(gemm_mma, cudaFuncAttributeMaxDynamicSharedMemorySize, SMEM_BYTES);
    gemm_mma<<<dim3(MPAD / BM, NPAD / BN, BATCH), 256, SMEM_BYTES>>>(out);

    int nr = BATCH * 3 * IMG * IMG;
    recon_kernel<<<(nr + 255) / 256, 256>>>(aux, out);
}

// round 9
// speedup vs baseline: 2.8225x; 1.3867x over previous
#include <cuda_runtime.h>
#include <cuda_fp16.h>
#include <cstdint>

#define BATCH 4
#define CCH   32
#define IMG   256
#define GRID_ 32
#define TDIM  33
#define TT    (TDIM*TDIM)   // 1089
#define KP    1152          // 1089 padded to mult of 64 (18*64)
#define MPAD  1152          // 9 * 128
#define NREAL 2112          // 33 * 64
#define NPAD  2176          // 17 * 128

#define OFF_MR  (BATCH*CCH*IMG*IMG)        // 8388608
#define OFF_RC  (OFF_MR + BATCH*IMG*IMG)   // 8650752

// ---------------- scratch ------------------------------------------------------
__device__ __half g_A[(size_t)BATCH * MPAD * KP];  // ~10.6 MB [b][t][k]
__device__ __half g_B[(size_t)BATCH * NPAD * KP];  // ~20.1 MB [b][n][k]
__device__ int    g_ids[BATCH * GRID_ * GRID_];
__device__ float  g_pv [4 * BATCH * 1024];
__device__ int    g_pix[4 * BATCH * 1024];

// ---------------- helpers ------------------------------------------------------
__device__ __forceinline__ void cp_async16(uint32_t saddr, const void* g) {
    asm volatile("cp.async.cg.shared.global [%0], [%1], 16;\n" :: "r"(saddr), "l"(g));
}

// ---------------- K1: A[t][k] = fp16(Atilde), coalesced via smem transpose -----
// grid (36*36, BATCH), block (32,8). Phase 1: t-contiguous (coalesced gx reads),
// Phase 2: transposed write, k-contiguous (coalesced 64B stores).
__global__ void prep_A(const float* __restrict__ cosd) {
    __shared__ __half sm[32][34];
    int b  = blockIdx.y;
    int tt = (blockIdx.x / 36) * 32;   // t tile base
    int kt = (blockIdx.x % 36) * 32;   // k tile base
    int tx = threadIdx.x, ty = threadIdx.y;
    const float* cb = cosd + (size_t)b * 1024 * 1024;

    #pragma unroll
    for (int i = 0; i < 4; i++) {
        int kl = ty + 8 * i;
        int kk = kt + kl;
        int t  = tt + tx;
        float s = 0.f;
        if (kk < TT && t < TT) {
            int my = kk / TDIM, mx = kk - my * TDIM;
            int Ty = t / TDIM,  Tx = t - Ty * TDIM;
            #pragma unroll
            for (int qy = 0; qy < 2; qy++) {
                int ny = my - qy, gy = Ty - qy;
                if ((unsigned)ny < GRID_ && (unsigned)gy < GRID_) {
                    #pragma unroll
                    for (int qx = 0; qx < 2; qx++) {
                        int nx = mx - qx, gx = Tx - qx;
                        if ((unsigned)nx < GRID_ && (unsigned)gx < GRID_)
                            s += cb[((ny * GRID_ + nx) * GRID_ + gy) * GRID_ + gx];
                    }
                }
            }
        }
        sm[kl][tx] = __float2half(s);
    }
    __syncthreads();
    #pragma unroll
    for (int i = 0; i < 4; i++) {
        int r = ty + 8 * i;            // t_local
        g_A[((size_t)b * MPAD + tt + r) * KP + kt + tx] = sm[tx][r];
    }
}

// ---------------- K2: B[n][k] = fp16(F), coalesced via smem transpose ----------
// grid (68*36, BATCH), block (32,8). Phase 1: n-contiguous (v contiguous reads).
__global__ void prep_B(const float* __restrict__ bimg, const float* __restrict__ mask) {
    __shared__ __half sm[32][34];
    int b  = blockIdx.y;
    int nt = (blockIdx.x / 36) * 32;   // n tile base
    int kt = (blockIdx.x % 36) * 32;   // k tile base
    int tx = threadIdx.x, ty = threadIdx.y;

    #pragma unroll
    for (int i = 0; i < 4; i++) {
        int kl = ty + 8 * i;
        int kk = kt + kl;
        int n  = nt + tx;
        float val = 0.f;
        if (kk < TT && n < NREAL) {
            int my = kk / TDIM, mx = kk - my * TDIM;
            int c  = n >> 6;
            int dy = (n >> 3) & 7;
            int dx = n & 7;
            int u = my * 8 + dy - 4; u = max(0, min(IMG - 1, u));
            int v = mx * 8 + dx - 4; v = max(0, min(IMG - 1, v));
            float m = mask[(b * IMG + u) * IMG + v];
            if (c < CCH) val = bimg[((b * CCH + c) * IMG + u) * IMG + v] * (1.f - m);
            else         val = m;
        }
        sm[kl][tx] = __float2half(val);
    }
    __syncthreads();
    #pragma unroll
    for (int i = 0; i < 4; i++) {
        int r = ty + 8 * i;            // n_local
        g_B[((size_t)b * NPAD + nt + r) * KP + kt + tx] = sm[tx][r];
    }
}

// ---------------- K4: HMMA GEMM 128x128x64, 2-stage, fp16 (unchanged) ----------
#define BM 128
#define BN 128
#define BK 64
#define NK (KP / BK)     // 18
#define SSTR 72          // fp16 row stride (144 B): conflict-free ldmatrix
#define ASTG (BM * SSTR)
#define STG  (2 * ASTG)
#define SMEM_BYTES (2 * STG * 2)   // 73728 B

__global__ void __launch_bounds__(256, 2) gemm_mma(float* __restrict__ out) {
    extern __shared__ __half sm[];

    const int tid = threadIdx.x, lane = tid & 31, wid = tid >> 5;
    const int wm = wid >> 2, wn = wid & 3;          // 2 x 4 warp grid
    const int b  = blockIdx.z;
    const int t0 = blockIdx.x * BM;
    const int n0 = blockIdx.y * BN;

    const __half* Ab = g_A + ((size_t)b * MPAD + t0) * KP;
    const __half* Bb = g_B + ((size_t)b * NPAD + n0) * KP;

    float acc[4][4][4];
    #pragma unroll
    for (int mi = 0; mi < 4; mi++)
        #pragma unroll
        for (int ni = 0; ni < 4; ni++)
            #pragma unroll
            for (int r = 0; r < 4; r++) acc[mi][ni][r] = 0.f;

    auto loadTile = [&](int kc, int st) {
        __half* As = sm + st * STG;
        __half* Bs = As + ASTG;
        #pragma unroll
        for (int q = 0; q < 4; q++) {
            int idx = tid + q * 256;
            int row = idx >> 3, cc = (idx & 7) * 8;
            cp_async16((uint32_t)__cvta_generic_to_shared(As + row * SSTR + cc),
                       Ab + (size_t)row * KP + kc * BK + cc);
        }
        #pragma unroll
        for (int q = 0; q < 4; q++) {
            int idx = tid + q * 256;
            int row = idx >> 3, cc = (idx & 7) * 8;
            cp_async16((uint32_t)__cvta_generic_to_shared(Bs + row * SSTR + cc),
                       Bb + (size_t)row * KP + kc * BK + cc);
        }
        asm volatile("cp.async.commit_group;");
    };

    loadTile(0, 0);
    for (int kt = 0; kt < NK; kt++) {
        if (kt + 1 < NK) {
            loadTile(kt + 1, (kt + 1) & 1);
            asm volatile("cp.async.wait_group 1;" ::: "memory");
        } else {
            asm volatile("cp.async.wait_group 0;" ::: "memory");
        }
        __syncthreads();

        const int s = kt & 1;
        __half* As = sm + s * STG;
        __half* Bs = As + ASTG;
        #pragma unroll
        for (int ks = 0; ks < 4; ks++) {
            uint32_t a[4][4], bf[2][4];
            #pragma unroll
            for (int mi = 0; mi < 4; mi++) {
                uint32_t ad = (uint32_t)__cvta_generic_to_shared(
                    As + (wm * 64 + mi * 16 + (lane & 15)) * SSTR + ks * 16 + (lane >> 4) * 8);
                asm volatile("ldmatrix.sync.aligned.m8n8.x4.shared.b16 {%0,%1,%2,%3}, [%4];"
                    : "=r"(a[mi][0]), "=r"(a[mi][1]), "=r"(a[mi][2]), "=r"(a[mi][3]) : "r"(ad));
            }
            #pragma unroll
            for (int nj = 0; nj < 2; nj++) {
                uint32_t bd = (uint32_t)__cvta_generic_to_shared(
                    Bs + (wn * 32 + nj * 16 + ((lane >> 4) & 1) * 8 + (lane & 7)) * SSTR
                       + ks * 16 + ((lane >> 3) & 1) * 8);
                asm volatile("ldmatrix.sync.aligned.m8n8.x4.shared.b16 {%0,%1,%2,%3}, [%4];"
                    : "=r"(bf[nj][0]), "=r"(bf[nj][1]), "=r"(bf[nj][2]), "=r"(bf[nj][3]) : "r"(bd));
            }
            #pragma unroll
            for (int mi = 0; mi < 4; mi++)
                #pragma unroll
                for (int ni = 0; ni < 4; ni++) {
                    int nj = ni >> 1, h = (ni & 1) * 2;
                    asm volatile(
                        "mma.sync.aligned.m16n8k16.row.col.f32.f16.f16.f32 "
                        "{%0,%1,%2,%3}, {%4,%5,%6,%7}, {%8,%9}, {%0,%1,%2,%3};"
                        : "+f"(acc[mi][ni][0]), "+f"(acc[mi][ni][1]),
                          "+f"(acc[mi][ni][2]), "+f"(acc[mi][ni][3])
                        : "r"(a[mi][0]), "r"(a[mi][1]), "r"(a[mi][2]), "r"(a[mi][3]),
                          "r"(bf[nj][h]), "r"(bf[nj][h + 1]));
                }
        }
        __syncthreads();
    }

    // ---- epilogue: D[t, n] -> cropped output / mask_recon ----
    #pragma unroll
    for (int mi = 0; mi < 4; mi++) {
        #pragma unroll
        for (int rr = 0; rr < 2; rr++) {
            int t = t0 + wm * 64 + mi * 16 + (lane >> 2) + rr * 8;
            if (t >= TT) continue;
            int Ty = t / TDIM, Tx = t - Ty * TDIM;
            int cnt = ((Ty >= 1) + (Ty <= 31)) * ((Tx >= 1) + (Tx <= 31));
            float inv = 1.f / (float)cnt;
            #pragma unroll
            for (int ni = 0; ni < 4; ni++) {
                int n = n0 + wn * 32 + ni * 8 + (lane & 3) * 2;
                int c = n >> 6;
                if (c > CCH) continue;      // N padding
                int dy = (n >> 3) & 7, dx = n & 7;
                int py = Ty * 8 + dy - 4;
                if ((unsigned)py >= 256u) continue;
                int px = Tx * 8 + dx - 4;
                float sc = (c < CCH) ? 1.f : inv;
                float* dst = (c < CCH)
                    ? out + (((size_t)(b * CCH + c)) * IMG + py) * IMG
                    : out + OFF_MR + (((size_t)b) * IMG + py) * IMG;
                float v0 = acc[mi][ni][rr * 2]     * sc;
                float v1 = acc[mi][ni][rr * 2 + 1] * sc;
                if ((unsigned)px < 255u) {
                    float2 v = make_float2(v0, v1);
                    *(float2*)(dst + px) = v;
                } else {
                    if ((unsigned)px < 256u)       dst[px]     = v0;
                    if ((unsigned)(px + 1) < 256u) dst[px + 1] = v1;
                }
            }
        }
    }
}

// ---------------- K5a: argmax partial (4-way n split) --------------------------
__global__ void argmax_part(const float* __restrict__ cosd) {
    int b  = blockIdx.z;
    int q  = blockIdx.y;
    int g  = blockIdx.x * 32 + threadIdx.x;
    int ty = threadIdx.y;
    const float* cb = cosd + (size_t)b * 1024 * 1024;
    float best = -3.4e38f;
    int   bi   = 0x7fffffff;
    int nbase = q * 256;
    for (int n0 = nbase + ty * 4; n0 < nbase + 256; n0 += 32) {
        float v0 = cb[(n0 + 0) * 1024 + g];
        float v1 = cb[(n0 + 1) * 1024 + g];
        float v2 = cb[(n0 + 2) * 1024 + g];
        float v3 = cb[(n0 + 3) * 1024 + g];
        if (v0 > best) { best = v0; bi = n0; }
        if (v1 > best) { best = v1; bi = n0 + 1; }
        if (v2 > best) { best = v2; bi = n0 + 2; }
        if (v3 > best) { best = v3; bi = n0 + 3; }
    }
    __shared__ float sv[8][32];
    __shared__ int   si[8][32];
    sv[ty][threadIdx.x] = best;
    si[ty][threadIdx.x] = bi;
    __syncthreads();
    if (ty == 0) {
        #pragma unroll
        for (int r = 1; r < 8; r++) {
            float v = sv[r][threadIdx.x];
            int   i2 = si[r][threadIdx.x];
            if (v > best || (v == best && i2 < bi)) { best = v; bi = i2; }
        }
        g_pv [(q * BATCH + b) * 1024 + g] = best;
        g_pix[(q * BATCH + b) * 1024 + g] = bi;
    }
}

// ---------------- K5b: argmax final reduce -------------------------------------
__global__ void argmax_final() {
    int idx = blockIdx.x * blockDim.x + threadIdx.x;   // b*1024 + g
    if (idx >= BATCH * 1024) return;
    int b = idx >> 10, g = idx & 1023;
    float best = -3.4e38f;
    int   bi   = 0x7fffffff;
    #pragma unroll
    for (int q = 0; q < 4; q++) {
        float v  = g_pv [(q * BATCH + b) * 1024 + g];
        int   i2 = g_pix[(q * BATCH + b) * 1024 + g];
        if (v > best || (v == best && i2 < bi)) { best = v; bi = i2; }
    }
    g_ids[idx] = bi;
}

// ---------------- K6: recon gather ---------------------------------------------
__global__ void recon_kernel(const float* __restrict__ aux, float* __restrict__ out) {
    int idx = blockIdx.x * blockDim.x + threadIdx.x;
    if (idx >= BATCH * 3 * IMG * IMG) return;
    int x = idx & 255;
    int y = (idx >> 8) & 255;
    int bc = idx >> 16;
    int b  = bc / 3;
    int py = y + 4, px = x + 4;
    int Ty = py >> 3, dy = py & 7;
    int Tx = px >> 3, dx = px & 7;
    const int*   ids = g_ids + b * 1024;
    const float* ab  = aux + (size_t)bc * IMG * IMG;
    float s = 0.f;
    #pragma unroll
    for (int qy = 0; qy < 2; qy++) {
        int gy = Ty - qy;
        if ((unsigned)gy >= GRID_) continue;
        int i = dy + 8 * qy;
        #pragma unroll
        for (int qx = 0; qx < 2; qx++) {
            int gx = Tx - qx;
            if ((unsigned)gx >= GRID_) continue;
            int j  = dx + 8 * qx;
            int id = ids[gy * 32 + gx];
            int u = (id >> 5) * 8 + i - 4; u = max(0, min(255, u));
            int v = (id & 31) * 8 + j - 4; v = max(0, min(255, v));
            s += ab[u * IMG + v];
        }
    }
    int cnty = (Ty >= 1) + (Ty <= 31);
    int cntx = (Tx >= 1) + (Tx <= 31);
    out[OFF_RC + idx] = s / (float)(cnty * cntx);
}

// ---------------- launch -------------------------------------------------------
extern "C" void kernel_launch(void* const* d_in, const int* in_sizes, int n_in,
                              void* d_out, int out_size) {
    const float* cosd = (const float*)d_in[0];
    const float* bimg = (const float*)d_in[1];
    const float* mask = (const float*)d_in[2];
    const float* aux  = (const float*)d_in[3];
    float* out = (float*)d_out;

    prep_A<<<dim3(36 * 36, BATCH), dim3(32, 8)>>>(cosd);
    prep_B<<<dim3(68 * 36, BATCH), dim3(32, 8)>>>(bimg, mask);

    argmax_part<<<dim3(32, 4, BATCH), dim3(32, 8)>>>(cosd);
    argmax_final<<<(BATCH * 1024 + 255) / 256, 256>>>();

    cudaFuncSetAttribute(gemm_mma, cudaFuncAttributeMaxDynamicSharedMemorySize, SMEM_BYTES);
    gemm_mma<<<dim3(MPAD / BM, NPAD / BN, BATCH), 256, SMEM_BYTES>>>(out);

    int nr = BATCH * 3 * IMG * IMG;
    recon_kernel<<<(nr + 255) / 256, 256>>>(aux, out);
}

// round 10
// speedup vs baseline: 2.9809x; 1.0561x over previous
#include <cuda_runtime.h>
#include <cuda_fp16.h>
#include <cstdint>

#define BATCH 4
#define CCH   32
#define IMG   256
#define GRID_ 32
#define TDIM  33
#define TT    (TDIM*TDIM)   // 1089
#define KP    1152          // 1089 padded to mult of 64 (18*64)
#define MPAD  1152          // 9 * 128
#define NREAL 2112          // 33 * 64  (no padding needed for BN=64)

#define OFF_MR  (BATCH*CCH*IMG*IMG)        // 8388608
#define OFF_RC  (OFF_MR + BATCH*IMG*IMG)   // 8650752

// ---------------- scratch ------------------------------------------------------
__device__ __half g_A[(size_t)BATCH * MPAD * KP];   // ~10.6 MB [b][t][k]
__device__ __half g_B[(size_t)BATCH * NREAL * KP];  // ~19.5 MB [b][n][k]
__device__ float  g_pv [4 * BATCH * 1024];
__device__ int    g_pix[4 * BATCH * 1024];

// ---------------- helpers ------------------------------------------------------
__device__ __forceinline__ void cp_async16(uint32_t saddr, const void* g) {
    asm volatile("cp.async.cg.shared.global [%0], [%1], 16;\n" :: "r"(saddr), "l"(g));
}

// ---------------- K1: A[t][k] = fp16(Atilde), coalesced via smem transpose -----
__global__ void prep_A(const float* __restrict__ cosd) {
    __shared__ __half sm[32][34];
    int b  = blockIdx.y;
    int tt = (blockIdx.x / 36) * 32;   // t tile base
    int kt = (blockIdx.x % 36) * 32;   // k tile base
    int tx = threadIdx.x, ty = threadIdx.y;
    const float* cb = cosd + (size_t)b * 1024 * 1024;

    #pragma unroll
    for (int i = 0; i < 4; i++) {
        int kl = ty + 8 * i;
        int kk = kt + kl;
        int t  = tt + tx;
        float s = 0.f;
        if (kk < TT && t < TT) {
            int my = kk / TDIM, mx = kk - my * TDIM;
            int Ty = t / TDIM,  Tx = t - Ty * TDIM;
            #pragma unroll
            for (int qy = 0; qy < 2; qy++) {
                int ny = my - qy, gy = Ty - qy;
                if ((unsigned)ny < GRID_ && (unsigned)gy < GRID_) {
                    #pragma unroll
                    for (int qx = 0; qx < 2; qx++) {
                        int nx = mx - qx, gx = Tx - qx;
                        if ((unsigned)nx < GRID_ && (unsigned)gx < GRID_)
                            s += cb[((ny * GRID_ + nx) * GRID_ + gy) * GRID_ + gx];
                    }
                }
            }
        }
        sm[kl][tx] = __float2half(s);
    }
    __syncthreads();
    #pragma unroll
    for (int i = 0; i < 4; i++) {
        int r = ty + 8 * i;            // t_local
        g_A[((size_t)b * MPAD + tt + r) * KP + kt + tx] = sm[tx][r];
    }
}

// ---------------- K2: B[n][k] = fp16(F), coalesced via smem transpose ----------
__global__ void prep_B(const float* __restrict__ bimg, const float* __restrict__ mask) {
    __shared__ __half sm[32][34];
    int b  = blockIdx.y;
    int nt = (blockIdx.x / 36) * 32;   // n tile base
    int kt = (blockIdx.x % 36) * 32;   // k tile base
    int tx = threadIdx.x, ty = threadIdx.y;

    #pragma unroll
    for (int i = 0; i < 4; i++) {
        int kl = ty + 8 * i;
        int kk = kt + kl;
        int n  = nt + tx;
        float val = 0.f;
        if (kk < TT) {
            int my = kk / TDIM, mx = kk - my * TDIM;
            int c  = n >> 6;
            int dy = (n >> 3) & 7;
            int dx = n & 7;
            int u = my * 8 + dy - 4; u = max(0, min(IMG - 1, u));
            int v = mx * 8 + dx - 4; v = max(0, min(IMG - 1, v));
            float m = mask[(b * IMG + u) * IMG + v];
            if (c < CCH) val = bimg[((b * CCH + c) * IMG + u) * IMG + v] * (1.f - m);
            else         val = m;
        }
        sm[kl][tx] = __float2half(val);
    }
    __syncthreads();
    #pragma unroll
    for (int i = 0; i < 4; i++) {
        int r = ty + 8 * i;            // n_local
        g_B[((size_t)b * NREAL + nt + r) * KP + kt + tx] = sm[tx][r];
    }
}

// ---------------- K4: HMMA GEMM 128x64x64, 2-stage, 3 CTA/SM -------------------
#define BM 128
#define BN 64
#define BK 64
#define NK (KP / BK)     // 18
#define SSTR 72          // fp16 row stride (144 B): conflict-free ldmatrix
#define ASTG (BM * SSTR)
#define BSTG (BN * SSTR)
#define STG  (ASTG + BSTG)
#define SMEM_BYTES (2 * STG * 2)   // 55296 B

__global__ void __launch_bounds__(256, 3) gemm_mma(float* __restrict__ out) {
    extern __shared__ __half sm[];

    const int tid = threadIdx.x, lane = tid & 31, wid = tid >> 5;
    const int wm = wid >> 1, wn = wid & 1;          // 4 x 2 warp grid (32x32 warp tile)
    const int b  = blockIdx.z;
    const int t0 = blockIdx.x * BM;
    const int n0 = blockIdx.y * BN;

    const __half* Ab = g_A + ((size_t)b * MPAD + t0) * KP;
    const __half* Bb = g_B + ((size_t)b * NREAL + n0) * KP;

    float acc[2][4][4];
    #pragma unroll
    for (int mi = 0; mi < 2; mi++)
        #pragma unroll
        for (int ni = 0; ni < 4; ni++)
            #pragma unroll
            for (int r = 0; r < 4; r++) acc[mi][ni][r] = 0.f;

    auto loadTile = [&](int kc, int st) {
        __half* As = sm + st * STG;
        __half* Bs = As + ASTG;
        #pragma unroll
        for (int q = 0; q < 4; q++) {
            int idx = tid + q * 256;
            int row = idx >> 3, cc = (idx & 7) * 8;
            cp_async16((uint32_t)__cvta_generic_to_shared(As + row * SSTR + cc),
                       Ab + (size_t)row * KP + kc * BK + cc);
        }
        #pragma unroll
        for (int q = 0; q < 2; q++) {
            int idx = tid + q * 256;
            int row = idx >> 3, cc = (idx & 7) * 8;
            cp_async16((uint32_t)__cvta_generic_to_shared(Bs + row * SSTR + cc),
                       Bb + (size_t)row * KP + kc * BK + cc);
        }
        asm volatile("cp.async.commit_group;");
    };

    loadTile(0, 0);
    for (int kt = 0; kt < NK; kt++) {
        if (kt + 1 < NK) {
            loadTile(kt + 1, (kt + 1) & 1);
            asm volatile("cp.async.wait_group 1;" ::: "memory");
        } else {
            asm volatile("cp.async.wait_group 0;" ::: "memory");
        }
        __syncthreads();

        const int s = kt & 1;
        __half* As = sm + s * STG;
        __half* Bs = As + ASTG;
        #pragma unroll
        for (int ks = 0; ks < 4; ks++) {
            uint32_t a[2][4], bf[2][4];
            #pragma unroll
            for (int mi = 0; mi < 2; mi++) {
                uint32_t ad = (uint32_t)__cvta_generic_to_shared(
                    As + (wm * 32 + mi * 16 + (lane & 15)) * SSTR + ks * 16 + (lane >> 4) * 8);
                asm volatile("ldmatrix.sync.aligned.m8n8.x4.shared.b16 {%0,%1,%2,%3}, [%4];"
                    : "=r"(a[mi][0]), "=r"(a[mi][1]), "=r"(a[mi][2]), "=r"(a[mi][3]) : "r"(ad));
            }
            #pragma unroll
            for (int nj = 0; nj < 2; nj++) {
                uint32_t bd = (uint32_t)__cvta_generic_to_shared(
                    Bs + (wn * 32 + nj * 16 + ((lane >> 4) & 1) * 8 + (lane & 7)) * SSTR
                       + ks * 16 + ((lane >> 3) & 1) * 8);
                asm volatile("ldmatrix.sync.aligned.m8n8.x4.shared.b16 {%0,%1,%2,%3}, [%4];"
                    : "=r"(bf[nj][0]), "=r"(bf[nj][1]), "=r"(bf[nj][2]), "=r"(bf[nj][3]) : "r"(bd));
            }
            #pragma unroll
            for (int mi = 0; mi < 2; mi++)
                #pragma unroll
                for (int ni = 0; ni < 4; ni++) {
                    int nj = ni >> 1, h = (ni & 1) * 2;
                    asm volatile(
                        "mma.sync.aligned.m16n8k16.row.col.f32.f16.f16.f32 "
                        "{%0,%1,%2,%3}, {%4,%5,%6,%7}, {%8,%9}, {%0,%1,%2,%3};"
                        : "+f"(acc[mi][ni][0]), "+f"(acc[mi][ni][1]),
                          "+f"(acc[mi][ni][2]), "+f"(acc[mi][ni][3])
                        : "r"(a[mi][0]), "r"(a[mi][1]), "r"(a[mi][2]), "r"(a[mi][3]),
                          "r"(bf[nj][h]), "r"(bf[nj][h + 1]));
                }
        }
        __syncthreads();
    }

    // ---- epilogue: D[t, n] -> cropped output / mask_recon (c == blockIdx.y) ---
    const int c = blockIdx.y;   // BN=64 => one channel per N-tile
    #pragma unroll
    for (int mi = 0; mi < 2; mi++) {
        #pragma unroll
        for (int rr = 0; rr < 2; rr++) {
            int t = t0 + wm * 32 + mi * 16 + (lane >> 2) + rr * 8;
            if (t >= TT) continue;
            int Ty = t / TDIM, Tx = t - Ty * TDIM;
            int cnt = ((Ty >= 1) + (Ty <= 31)) * ((Tx >= 1) + (Tx <= 31));
            float sc = (c < CCH) ? 1.f : 1.f / (float)cnt;
            float* dstrow = (c < CCH)
                ? out + (((size_t)(b * CCH + c)) * IMG) * IMG
                : out + OFF_MR + (((size_t)b) * IMG) * IMG;
            #pragma unroll
            for (int ni = 0; ni < 4; ni++) {
                int off = wn * 32 + ni * 8 + (lane & 3) * 2;   // 0..63 within channel
                int dy = off >> 3, dx = off & 7;
                int py = Ty * 8 + dy - 4;
                if ((unsigned)py >= 256u) continue;
                int px = Tx * 8 + dx - 4;
                float* dst = dstrow + (size_t)py * IMG;
                float v0 = acc[mi][ni][rr * 2]     * sc;
                float v1 = acc[mi][ni][rr * 2 + 1] * sc;
                if ((unsigned)px < 255u) {
                    *(float2*)(dst + px) = make_float2(v0, v1);
                } else {
                    if ((unsigned)px < 256u)       dst[px]     = v0;
                    if ((unsigned)(px + 1) < 256u) dst[px + 1] = v1;
                }
            }
        }
    }
}

// ---------------- K5: argmax partial (4-way n split) ---------------------------
__global__ void argmax_part(const float* __restrict__ cosd) {
    int b  = blockIdx.z;
    int q  = blockIdx.y;
    int g  = blockIdx.x * 32 + threadIdx.x;
    int ty = threadIdx.y;
    const float* cb = cosd + (size_t)b * 1024 * 1024;
    float best = -3.4e38f;
    int   bi   = 0x7fffffff;
    int nbase = q * 256;
    for (int n0 = nbase + ty * 4; n0 < nbase + 256; n0 += 32) {
        float v0 = cb[(n0 + 0) * 1024 + g];
        float v1 = cb[(n0 + 1) * 1024 + g];
        float v2 = cb[(n0 + 2) * 1024 + g];
        float v3 = cb[(n0 + 3) * 1024 + g];
        if (v0 > best) { best = v0; bi = n0; }
        if (v1 > best) { best = v1; bi = n0 + 1; }
        if (v2 > best) { best = v2; bi = n0 + 2; }
        if (v3 > best) { best = v3; bi = n0 + 3; }
    }
    __shared__ float sv[8][32];
    __shared__ int   si[8][32];
    sv[ty][threadIdx.x] = best;
    si[ty][threadIdx.x] = bi;
    __syncthreads();
    if (ty == 0) {
        #pragma unroll
        for (int r = 1; r < 8; r++) {
            float v = sv[r][threadIdx.x];
            int   i2 = si[r][threadIdx.x];
            if (v > best || (v == best && i2 < bi)) { best = v; bi = i2; }
        }
        g_pv [(q * BATCH + b) * 1024 + g] = best;
        g_pix[(q * BATCH + b) * 1024 + g] = bi;
    }
}

// ---------------- K6: recon gather (with inline argmax final reduce) -----------
// One block = one output row (bc, y). First 64 threads reduce the <=64 needed
// grid cells' argmax from the 4 partials into smem, then all gather.
__global__ void recon_kernel(const float* __restrict__ aux, float* __restrict__ out) {
    __shared__ int sid[2][32];
    int row = blockIdx.x;          // bc * 256 + y
    int y   = row & 255;
    int bc  = row >> 8;
    int b   = bc / 3;
    int x   = threadIdx.x;
    int py  = y + 4;
    int Ty  = py >> 3, dy = py & 7;

    // cooperative argmax finalize for gy in {Ty-1, Ty}, gx in [0,32)
    if (threadIdx.x < 64) {
        int which = threadIdx.x >> 5;          // 0 -> Ty-1, 1 -> Ty
        int gy = Ty - 1 + which;
        int gx = threadIdx.x & 31;
        int id = 0;
        if ((unsigned)gy < GRID_) {
            int g = gy * 32 + gx;
            float best = -3.4e38f; int bi = 0x7fffffff;
            #pragma unroll
            for (int q = 0; q < 4; q++) {
                float v  = g_pv [(q * BATCH + b) * 1024 + g];
                int   i2 = g_pix[(q * BATCH + b) * 1024 + g];
                if (v > best || (v == best && i2 < bi)) { best = v; bi = i2; }
            }
            id = bi;
        }
        sid[which][gx] = id;
    }
    __syncthreads();

    int px = x + 4;
    int Tx = px >> 3, dx = px & 7;
    const float* ab = aux + (size_t)bc * IMG * IMG;
    float s = 0.f;
    #pragma unroll
    for (int qy = 0; qy < 2; qy++) {
        int gy = Ty - qy;
        if ((unsigned)gy >= GRID_) continue;
        int i = dy + 8 * qy;
        #pragma unroll
        for (int qx = 0; qx < 2; qx++) {
            int gx = Tx - qx;
            if ((unsigned)gx >= GRID_) continue;
            int j  = dx + 8 * qx;
            int id = sid[1 - qy][gx];
            int u = (id >> 5) * 8 + i - 4; u = max(0, min(255, u));
            int v = (id & 31) * 8 + j - 4; v = max(0, min(255, v));
            s += ab[u * IMG + v];
        }
    }
    int cnty = (Ty >= 1) + (Ty <= 31);
    int cntx = (Tx >= 1) + (Tx <= 31);
    out[OFF_RC + row * 256 + x] = s / (float)(cnty * cntx);
}

// ---------------- launch -------------------------------------------------------
extern "C" void kernel_launch(void* const* d_in, const int* in_sizes, int n_in,
                              void* d_out, int out_size) {
    const float* cosd = (const float*)d_in[0];
    const float* bimg = (const float*)d_in[1];
    const float* mask = (const float*)d_in[2];
    const float* aux  = (const float*)d_in[3];
    float* out = (float*)d_out;

    prep_A<<<dim3(36 * 36, BATCH), dim3(32, 8)>>>(cosd);
    prep_B<<<dim3(66 * 36, BATCH), dim3(32, 8)>>>(bimg, mask);

    argmax_part<<<dim3(32, 4, BATCH), dim3(32, 8)>>>(cosd);

    cudaFuncSetAttribute(gemm_mma, cudaFuncAttributeMaxDynamicSharedMemorySize, SMEM_BYTES);
    gemm_mma<<<dim3(MPAD / BM, NREAL / BN, BATCH), 256, SMEM_BYTES>>>(out);

    recon_kernel<<<BATCH * 3 * IMG, 256>>>(aux, out);
}

// round 11
// speedup vs baseline: 2.9822x; 1.0004x over previous
#include <cuda_runtime.h>
#include <cuda_fp16.h>
#include <cstdint>

#define BATCH 4
#define CCH   32
#define IMG   256
#define GRID_ 32
#define TDIM  33
#define TT    (TDIM*TDIM)   // 1089
#define KP    1152          // 1089 padded to mult of 64 (18*64)
#define MPAD  1152          // 9 * 128
#define NREAL 2112          // 33 * 64  (no padding needed for BN=64)

#define OFF_MR  (BATCH*CCH*IMG*IMG)        // 8388608
#define OFF_RC  (OFF_MR + BATCH*IMG*IMG)   // 8650752

// ---------------- scratch ------------------------------------------------------
__device__ __half g_A[(size_t)BATCH * MPAD * KP];   // ~10.6 MB [b][t][k]
__device__ __half g_B[(size_t)BATCH * NREAL * KP];  // ~19.5 MB [b][n][k]
__device__ float  g_pv [4 * BATCH * 1024];
__device__ int    g_pix[4 * BATCH * 1024];

// ---------------- helpers ------------------------------------------------------
__device__ __forceinline__ void cp_async16(uint32_t saddr, const void* g) {
    asm volatile("cp.async.cg.shared.global [%0], [%1], 16;\n" :: "r"(saddr), "l"(g));
}

// ---------------- K1: A[t][k] = fp16(Atilde), coalesced via smem transpose -----
__global__ void prep_A(const float* __restrict__ cosd) {
    __shared__ __half sm[32][34];
    int b  = blockIdx.y;
    int tt = (blockIdx.x / 36) * 32;   // t tile base
    int kt = (blockIdx.x % 36) * 32;   // k tile base
    int tx = threadIdx.x, ty = threadIdx.y;
    const float* cb = cosd + (size_t)b * 1024 * 1024;

    #pragma unroll
    for (int i = 0; i < 4; i++) {
        int kl = ty + 8 * i;
        int kk = kt + kl;
        int t  = tt + tx;
        float s = 0.f;
        if (kk < TT && t < TT) {
            int my = kk / TDIM, mx = kk - my * TDIM;
            int Ty = t / TDIM,  Tx = t - Ty * TDIM;
            #pragma unroll
            for (int qy = 0; qy < 2; qy++) {
                int ny = my - qy, gy = Ty - qy;
                if ((unsigned)ny < GRID_ && (unsigned)gy < GRID_) {
                    #pragma unroll
                    for (int qx = 0; qx < 2; qx++) {
                        int nx = mx - qx, gx = Tx - qx;
                        if ((unsigned)nx < GRID_ && (unsigned)gx < GRID_)
                            s += cb[((ny * GRID_ + nx) * GRID_ + gy) * GRID_ + gx];
                    }
                }
            }
        }
        sm[kl][tx] = __float2half(s);
    }
    __syncthreads();
    #pragma unroll
    for (int i = 0; i < 4; i++) {
        int r = ty + 8 * i;            // t_local
        g_A[((size_t)b * MPAD + tt + r) * KP + kt + tx] = sm[tx][r];
    }
}

// ---------------- K2: B[n][k] = fp16(F), coalesced via smem transpose ----------
__global__ void prep_B(const float* __restrict__ bimg, const float* __restrict__ mask) {
    __shared__ __half sm[32][34];
    int b  = blockIdx.y;
    int nt = (blockIdx.x / 36) * 32;   // n tile base
    int kt = (blockIdx.x % 36) * 32;   // k tile base
    int tx = threadIdx.x, ty = threadIdx.y;

    #pragma unroll
    for (int i = 0; i < 4; i++) {
        int kl = ty + 8 * i;
        int kk = kt + kl;
        int n  = nt + tx;
        float val = 0.f;
        if (kk < TT) {
            int my = kk / TDIM, mx = kk - my * TDIM;
            int c  = n >> 6;
            int dy = (n >> 3) & 7;
            int dx = n & 7;
            int u = my * 8 + dy - 4; u = max(0, min(IMG - 1, u));
            int v = mx * 8 + dx - 4; v = max(0, min(IMG - 1, v));
            float m = mask[(b * IMG + u) * IMG + v];
            if (c < CCH) val = bimg[((b * CCH + c) * IMG + u) * IMG + v] * (1.f - m);
            else         val = m;
        }
        sm[kl][tx] = __float2half(val);
    }
    __syncthreads();
    #pragma unroll
    for (int i = 0; i < 4; i++) {
        int r = ty + 8 * i;            // n_local
        g_B[((size_t)b * NREAL + nt + r) * KP + kt + tx] = sm[tx][r];
    }
}

// ---------------- K4: HMMA GEMM 128x64x64, 2-stage, 3 CTA/SM -------------------
#define BM 128
#define BN 64
#define BK 64
#define NK (KP / BK)     // 18
#define SSTR 72          // fp16 row stride (144 B): conflict-free ldmatrix
#define ASTG (BM * SSTR)
#define BSTG (BN * SSTR)
#define STG  (ASTG + BSTG)
#define SMEM_BYTES (2 * STG * 2)   // 55296 B

__global__ void __launch_bounds__(256, 3) gemm_mma(float* __restrict__ out) {
    extern __shared__ __half sm[];

    const int tid = threadIdx.x, lane = tid & 31, wid = tid >> 5;
    const int wm = wid >> 1, wn = wid & 1;          // 4 x 2 warp grid (32x32 warp tile)
    const int b  = blockIdx.z;
    const int t0 = blockIdx.x * BM;
    const int n0 = blockIdx.y * BN;

    const __half* Ab = g_A + ((size_t)b * MPAD + t0) * KP;
    const __half* Bb = g_B + ((size_t)b * NREAL + n0) * KP;

    float acc[2][4][4];
    #pragma unroll
    for (int mi = 0; mi < 2; mi++)
        #pragma unroll
        for (int ni = 0; ni < 4; ni++)
            #pragma unroll
            for (int r = 0; r < 4; r++) acc[mi][ni][r] = 0.f;

    auto loadTile = [&](int kc, int st) {
        __half* As = sm + st * STG;
        __half* Bs = As + ASTG;
        #pragma unroll
        for (int q = 0; q < 4; q++) {
            int idx = tid + q * 256;
            int row = idx >> 3, cc = (idx & 7) * 8;
            cp_async16((uint32_t)__cvta_generic_to_shared(As + row * SSTR + cc),
                       Ab + (size_t)row * KP + kc * BK + cc);
        }
        #pragma unroll
        for (int q = 0; q < 2; q++) {
            int idx = tid + q * 256;
            int row = idx >> 3, cc = (idx & 7) * 8;
            cp_async16((uint32_t)__cvta_generic_to_shared(Bs + row * SSTR + cc),
                       Bb + (size_t)row * KP + kc * BK + cc);
        }
        asm volatile("cp.async.commit_group;");
    };

    loadTile(0, 0);
    for (int kt = 0; kt < NK; kt++) {
        if (kt + 1 < NK) {
            loadTile(kt + 1, (kt + 1) & 1);
            asm volatile("cp.async.wait_group 1;" ::: "memory");
        } else {
            asm volatile("cp.async.wait_group 0;" ::: "memory");
        }
        __syncthreads();

        const int s = kt & 1;
        __half* As = sm + s * STG;
        __half* Bs = As + ASTG;
        #pragma unroll
        for (int ks = 0; ks < 4; ks++) {
            uint32_t a[2][4], bf[2][4];
            #pragma unroll
            for (int mi = 0; mi < 2; mi++) {
                uint32_t ad = (uint32_t)__cvta_generic_to_shared(
                    As + (wm * 32 + mi * 16 + (lane & 15)) * SSTR + ks * 16 + (lane >> 4) * 8);
                asm volatile("ldmatrix.sync.aligned.m8n8.x4.shared.b16 {%0,%1,%2,%3}, [%4];"
                    : "=r"(a[mi][0]), "=r"(a[mi][1]), "=r"(a[mi][2]), "=r"(a[mi][3]) : "r"(ad));
            }
            #pragma unroll
            for (int nj = 0; nj < 2; nj++) {
                uint32_t bd = (uint32_t)__cvta_generic_to_shared(
                    Bs + (wn * 32 + nj * 16 + ((lane >> 4) & 1) * 8 + (lane & 7)) * SSTR
                       + ks * 16 + ((lane >> 3) & 1) * 8);
                asm volatile("ldmatrix.sync.aligned.m8n8.x4.shared.b16 {%0,%1,%2,%3}, [%4];"
                    : "=r"(bf[nj][0]), "=r"(bf[nj][1]), "=r"(bf[nj][2]), "=r"(bf[nj][3]) : "r"(bd));
            }
            #pragma unroll
            for (int mi = 0; mi < 2; mi++)
                #pragma unroll
                for (int ni = 0; ni < 4; ni++) {
                    int nj = ni >> 1, h = (ni & 1) * 2;
                    asm volatile(
                        "mma.sync.aligned.m16n8k16.row.col.f32.f16.f16.f32 "
                        "{%0,%1,%2,%3}, {%4,%5,%6,%7}, {%8,%9}, {%0,%1,%2,%3};"
                        : "+f"(acc[mi][ni][0]), "+f"(acc[mi][ni][1]),
                          "+f"(acc[mi][ni][2]), "+f"(acc[mi][ni][3])
                        : "r"(a[mi][0]), "r"(a[mi][1]), "r"(a[mi][2]), "r"(a[mi][3]),
                          "r"(bf[nj][h]), "r"(bf[nj][h + 1]));
                }
        }
        __syncthreads();
    }

    // ---- epilogue: D[t, n] -> cropped output / mask_recon (c == blockIdx.y) ---
    const int c = blockIdx.y;   // BN=64 => one channel per N-tile
    #pragma unroll
    for (int mi = 0; mi < 2; mi++) {
        #pragma unroll
        for (int rr = 0; rr < 2; rr++) {
            int t = t0 + wm * 32 + mi * 16 + (lane >> 2) + rr * 8;
            if (t >= TT) continue;
            int Ty = t / TDIM, Tx = t - Ty * TDIM;
            int cnt = ((Ty >= 1) + (Ty <= 31)) * ((Tx >= 1) + (Tx <= 31));
            float sc = (c < CCH) ? 1.f : 1.f / (float)cnt;
            float* dstrow = (c < CCH)
                ? out + (((size_t)(b * CCH + c)) * IMG) * IMG
                : out + OFF_MR + (((size_t)b) * IMG) * IMG;
            #pragma unroll
            for (int ni = 0; ni < 4; ni++) {
                int off = wn * 32 + ni * 8 + (lane & 3) * 2;   // 0..63 within channel
                int dy = off >> 3, dx = off & 7;
                int py = Ty * 8 + dy - 4;
                if ((unsigned)py >= 256u) continue;
                int px = Tx * 8 + dx - 4;
                float* dst = dstrow + (size_t)py * IMG;
                float v0 = acc[mi][ni][rr * 2]     * sc;
                float v1 = acc[mi][ni][rr * 2 + 1] * sc;
                if ((unsigned)px < 255u) {
                    *(float2*)(dst + px) = make_float2(v0, v1);
                } else {
                    if ((unsigned)px < 256u)       dst[px]     = v0;
                    if ((unsigned)(px + 1) < 256u) dst[px + 1] = v1;
                }
            }
        }
    }
}

// ---------------- K5: argmax partial (4-way n split) ---------------------------
__global__ void argmax_part(const float* __restrict__ cosd) {
    int b  = blockIdx.z;
    int q  = blockIdx.y;
    int g  = blockIdx.x * 32 + threadIdx.x;
    int ty = threadIdx.y;
    const float* cb = cosd + (size_t)b * 1024 * 1024;
    float best = -3.4e38f;
    int   bi   = 0x7fffffff;
    int nbase = q * 256;
    for (int n0 = nbase + ty * 4; n0 < nbase + 256; n0 += 32) {
        float v0 = cb[(n0 + 0) * 1024 + g];
        float v1 = cb[(n0 + 1) * 1024 + g];
        float v2 = cb[(n0 + 2) * 1024 + g];
        float v3 = cb[(n0 + 3) * 1024 + g];
        if (v0 > best) { best = v0; bi = n0; }
        if (v1 > best) { best = v1; bi = n0 + 1; }
        if (v2 > best) { best = v2; bi = n0 + 2; }
        if (v3 > best) { best = v3; bi = n0 + 3; }
    }
    __shared__ float sv[8][32];
    __shared__ int   si[8][32];
    sv[ty][threadIdx.x] = best;
    si[ty][threadIdx.x] = bi;
    __syncthreads();
    if (ty == 0) {
        #pragma unroll
        for (int r = 1; r < 8; r++) {
            float v = sv[r][threadIdx.x];
            int   i2 = si[r][threadIdx.x];
            if (v > best || (v == best && i2 < bi)) { best = v; bi = i2; }
        }
        g_pv [(q * BATCH + b) * 1024 + g] = best;
        g_pix[(q * BATCH + b) * 1024 + g] = bi;
    }
}

// ---------------- K6: recon gather (with inline argmax final reduce) -----------
// One block = one output row (bc, y). First 64 threads reduce the <=64 needed
// grid cells' argmax from the 4 partials into smem, then all gather.
__global__ void recon_kernel(const float* __restrict__ aux, float* __restrict__ out) {
    __shared__ int sid[2][32];
    int row = blockIdx.x;          // bc * 256 + y
    int y   = row & 255;
    int bc  = row >> 8;
    int b   = bc / 3;
    int x   = threadIdx.x;
    int py  = y + 4;
    int Ty  = py >> 3, dy = py & 7;

    // cooperative argmax finalize for gy in {Ty-1, Ty}, gx in [0,32)
    if (threadIdx.x < 64) {
        int which = threadIdx.x >> 5;          // 0 -> Ty-1, 1 -> Ty
        int gy = Ty - 1 + which;
        int gx = threadIdx.x & 31;
        int id = 0;
        if ((unsigned)gy < GRID_) {
            int g = gy * 32 + gx;
            float best = -3.4e38f; int bi = 0x7fffffff;
            #pragma unroll
            for (int q = 0; q < 4; q++) {
                float v  = g_pv [(q * BATCH + b) * 1024 + g];
                int   i2 = g_pix[(q * BATCH + b) * 1024 + g];
                if (v > best || (v == best && i2 < bi)) { best = v; bi = i2; }
            }
            id = bi;
        }
        sid[which][gx] = id;
    }
    __syncthreads();

    int px = x + 4;
    int Tx = px >> 3, dx = px & 7;
    const float* ab = aux + (size_t)bc * IMG * IMG;
    float s = 0.f;
    #pragma unroll
    for (int qy = 0; qy < 2; qy++) {
        int gy = Ty - qy;
        if ((unsigned)gy >= GRID_) continue;
        int i = dy + 8 * qy;
        #pragma unroll
        for (int qx = 0; qx < 2; qx++) {
            int gx = Tx - qx;
            if ((unsigned)gx >= GRID_) continue;
            int j  = dx + 8 * qx;
            int id = sid[1 - qy][gx];
            int u = (id >> 5) * 8 + i - 4; u = max(0, min(255, u));
            int v = (id & 31) * 8 + j - 4; v = max(0, min(255, v));
            s += ab[u * IMG + v];
        }
    }
    int cnty = (Ty >= 1) + (Ty <= 31);
    int cntx = (Tx >= 1) + (Tx <= 31);
    out[OFF_RC + row * 256 + x] = s / (float)(cnty * cntx);
}

// ---------------- launch -------------------------------------------------------
extern "C" void kernel_launch(void* const* d_in, const int* in_sizes, int n_in,
                              void* d_out, int out_size) {
    const float* cosd = (const float*)d_in[0];
    const float* bimg = (const float*)d_in[1];
    const float* mask = (const float*)d_in[2];
    const float* aux  = (const float*)d_in[3];
    float* out = (float*)d_out;

    prep_A<<<dim3(36 * 36, BATCH), dim3(32, 8)>>>(cosd);
    prep_B<<<dim3(66 * 36, BATCH), dim3(32, 8)>>>(bimg, mask);

    argmax_part<<<dim3(32, 4, BATCH), dim3(32, 8)>>>(cosd);

    cudaFuncSetAttribute(gemm_mma, cudaFuncAttributeMaxDynamicSharedMemorySize, SMEM_BYTES);
    gemm_mma<<<dim3(MPAD / BM, NREAL / BN, BATCH), 256, SMEM_BYTES>>>(out);

    recon_kernel<<<BATCH * 3 * IMG, 256>>>(aux, out);
}